// round 12
// baseline (speedup 1.0000x reference)
#include <cuda_runtime.h>
#include <cuda_fp16.h>
#include <math.h>
#include <stdint.h>

// ---------------- problem constants ----------------
#define Bb   2
#define Ss   1024
#define Dd   1024
#define Hh   16
#define HDd  64
#define MMm  16
#define WWw  8
#define RMm  8
#define CRc  8
#define FFD  4096
#define ROWS (Bb*Ss)          // 2048
#define VPW  1408             // v(1024) | qm(16) km(16) qc(128) kc(128) pad

// ---------------- scratch ----------------
__device__ __half g_xh   [ROWS*Dd];
__device__ __half g_wcat [Dd*VPW];
__device__ float  g_bcat [VPW];
__device__ __half g_vph  [ROWS*VPW];
__device__ __half g_owh  [Dd*Dd];
__device__ __half g_w1h  [Dd*FFD];
__device__ __half g_w2h  [FFD*Dd];
__device__ __half g_ctxh [ROWS*Dd];
__device__ __half g_hch  [ROWS*Dd];
__device__ __half g_ffnh [ROWS*FFD];
__device__ float  g_pp   [64*2048];
__device__ float  g_pool [Bb*Dd];
__device__ float  g_wts  [Bb*Hh*MMm];
__device__ float  g_ckr  [Bb*Hh*Ss];
__device__ float  g_ao   [ROWS*Dd];
__device__ float  g_h    [ROWS*Dd];
__device__ float  g_f2   [ROWS*Dd];

// ---------------- helpers ----------------
__device__ __forceinline__ uint32_t smem_u32(const void* p) {
    uint32_t a;
    asm("{ .reg .u64 t; cvta.to.shared.u64 t, %1; cvt.u32.u64 %0, t; }" : "=r"(a) : "l"(p));
    return a;
}
__device__ __forceinline__ void mma_f16(float* c, const uint32_t* a, const uint32_t* b) {
    asm volatile(
        "mma.sync.aligned.m16n8k16.row.col.f32.f16.f16.f32 "
        "{%0,%1,%2,%3}, {%4,%5,%6,%7}, {%8,%9}, {%0,%1,%2,%3};"
        : "+f"(c[0]), "+f"(c[1]), "+f"(c[2]), "+f"(c[3])
        : "r"(a[0]), "r"(a[1]), "r"(a[2]), "r"(a[3]), "r"(b[0]), "r"(b[1]));
}
__device__ __forceinline__ void cpa16(uint32_t dst, const void* src) {
    asm volatile("cp.async.cg.shared.global [%0], [%1], 16;" :: "r"(dst), "l"(src));
}
#define CPA_COMMIT() asm volatile("cp.async.commit_group;" ::: "memory")
__device__ __forceinline__ uint32_t h2u(float a, float b) {
    __half2 h = __floats2half2_rn(a, b);
    return *(uint32_t*)&h;
}
__device__ __forceinline__ void st2(float* p, float a, float b) { *(float2*)p = make_float2(a, b); }
__device__ __forceinline__ void st2(__half* p, float a, float b) { *(__half2*)p = __floats2half2_rn(a, b); }

// ---------------- fp16 GEMM: C[M,0..N) = A[M,K] @ B[K,N] + bias ----------------
// A half K-major; B half row-major [K][N] (stride N). C row stride ldc.
// CTA tile (MT*32) x 128, K-tile 64, 3-stage cp.async pipeline.
// MT=4: 128x128 tile (32 KB/stage); MT=2: 64x128 tile (24 KB/stage).
template<int MT, bool GELU, typename OT>
__global__ void __launch_bounds__(256, 2)
gemmh(const __half* __restrict__ A, const __half* __restrict__ B,
      const float* __restrict__ bias, OT* __restrict__ C,
      int M, int N, int K, int ldc)
{
    extern __shared__ __align__(16) unsigned char smem[];
    const int tid = threadIdx.x, lane = tid & 31, warp = tid >> 5;
    const int wm = warp & 1, wn = warp >> 1;       // warp tile (MT*16) x 32
    const int rr = lane >> 2, cl = lane & 3;
    const int m0 = blockIdx.y * (MT * 32), n0 = blockIdx.x * 128;
    const __half* Arow = A + (size_t)m0 * K;
    const __half* Bcol = B + n0;
    const uint32_t sbase = smem_u32(smem);
    const int T = K >> 6;
    const int ABYTES = MT * 4096;                  // A rows (MT*32) x 128B
    const int STAGE  = ABYTES + 16384;

    float acc[MT][4][4];
    #pragma unroll
    for (int mt = 0; mt < MT; mt++)
        #pragma unroll
        for (int nt = 0; nt < 4; nt++)
            #pragma unroll
            for (int q = 0; q < 4; q++) acc[mt][nt][q] = 0.f;

    auto stage = [&](int t) {
        if (t < T) {
            const uint32_t sb = sbase + (t % 3) * STAGE;
            const int k0 = t << 6;
            // A: (MT*32) rows x 128B (8 units of 16B)
            #pragma unroll
            for (int q = 0; q < MT; q++) {
                int ch = q * 256 + tid;
                int row = ch >> 3, u = ch & 7;
                uint32_t off = row * 128 + ((u ^ (row & 7)) << 4);
                cpa16(sb + off, Arow + (size_t)row * K + k0 + u * 8);
            }
            // B: 64 rows x 256B (16 units)
            #pragma unroll
            for (int q = 0; q < 4; q++) {
                int ch = q * 256 + tid;
                int k = ch >> 4, u = ch & 15;
                uint32_t off = k * 256 + ((u ^ (k & 7)) << 4);
                cpa16(sb + ABYTES + off, Bcol + (size_t)(k0 + k) * N + u * 8);
            }
        }
        CPA_COMMIT();      // always commit (empty group past the end)
    };

    stage(0); stage(1);
    for (int t = 0; t < T; t++) {
        asm volatile("cp.async.wait_group 1;" ::: "memory");
        __syncthreads();
        stage(t + 2);      // overwrites slot (t-1)%3 — its reads finished before barrier
        const uint32_t sA = sbase + (t % 3) * STAGE;
        const uint32_t sB = sA + ABYTES;

        #pragma unroll
        for (int kk = 0; kk < 4; kk++) {
            uint32_t af[MT][4], bf[4][2];
            #pragma unroll
            for (int mt = 0; mt < MT; mt++) {
                int row = wm * (MT*16) + mt * 16 + ((lane >> 3) & 1) * 8 + (lane & 7);
                int unit = kk * 2 + (lane >> 4);
                uint32_t addr = sA + row * 128 + ((unit ^ (row & 7)) << 4);
                asm volatile("ldmatrix.sync.aligned.m8n8.x4.shared.b16 {%0,%1,%2,%3}, [%4];"
                             : "=r"(af[mt][0]), "=r"(af[mt][1]), "=r"(af[mt][2]), "=r"(af[mt][3])
                             : "r"(addr));
            }
            #pragma unroll
            for (int nt = 0; nt < 4; nt += 2) {
                int rowk = kk * 16 + (lane & 15);
                int unitn = wn * 4 + nt + (lane >> 4);
                uint32_t addr = sB + rowk * 256 + ((unitn ^ (rowk & 7)) << 4);
                asm volatile("ldmatrix.sync.aligned.m8n8.x4.trans.shared.b16 {%0,%1,%2,%3}, [%4];"
                             : "=r"(bf[nt][0]), "=r"(bf[nt][1]), "=r"(bf[nt+1][0]), "=r"(bf[nt+1][1])
                             : "r"(addr));
            }
            #pragma unroll
            for (int mt = 0; mt < MT; mt++)
                #pragma unroll
                for (int nt = 0; nt < 4; nt++)
                    mma_f16(acc[mt][nt], af[mt], bf[nt]);
        }
    }

    #pragma unroll
    for (int mt = 0; mt < MT; mt++) {
        #pragma unroll
        for (int nt = 0; nt < 4; nt++) {
            int r  = m0 + wm * (MT*16) + mt * 16 + rr;
            int cc = n0 + wn * 32 + nt * 8 + 2 * cl;
            float b0 = bias ? bias[cc]     : 0.f;
            float b1 = bias ? bias[cc + 1] : 0.f;
            float v0 = acc[mt][nt][0] + b0;
            float v1 = acc[mt][nt][1] + b1;
            float v2 = acc[mt][nt][2] + b0;
            float v3 = acc[mt][nt][3] + b1;
            if (GELU) {
                v0 = 0.5f * v0 * (1.f + erff(v0 * 0.70710678118654752f));
                v1 = 0.5f * v1 * (1.f + erff(v1 * 0.70710678118654752f));
                v2 = 0.5f * v2 * (1.f + erff(v2 * 0.70710678118654752f));
                v3 = 0.5f * v3 * (1.f + erff(v3 * 0.70710678118654752f));
            }
            st2(C + (size_t)r * ldc + cc,       v0, v1);
            st2(C + (size_t)(r + 8) * ldc + cc, v2, v3);
        }
    }
}

// ---------------- prep kernels ----------------
__device__ __forceinline__ void cvt16(const float* __restrict__ src, __half* __restrict__ dst, int i)
{
    float4 v0 = *(const float4*)(src + i);
    float4 v1 = *(const float4*)(src + i + 4);
    float4 v2 = *(const float4*)(src + i + 8);
    float4 v3 = *(const float4*)(src + i + 12);
    uint4 o0, o1;
    o0.x = h2u(v0.x, v0.y); o0.y = h2u(v0.z, v0.w);
    o0.z = h2u(v1.x, v1.y); o0.w = h2u(v1.z, v1.w);
    o1.x = h2u(v2.x, v2.y); o1.y = h2u(v2.z, v2.w);
    o1.z = h2u(v3.x, v3.y); o1.w = h2u(v3.z, v3.w);
    *(uint4*)(dst + i)     = o0;
    *(uint4*)(dst + i + 8) = o1;
}

__global__ void cvth_k(const float* __restrict__ src, __half* __restrict__ dst)
{
    cvt16(src, dst, (blockIdx.x * 256 + threadIdx.x) * 16);
}

__global__ void cvt3_k(const float* __restrict__ a, __half* __restrict__ da,
                       const float* __restrict__ b, __half* __restrict__ db,
                       const float* __restrict__ c, __half* __restrict__ dc)
{
    int blk = blockIdx.x;
    const float* src; __half* dst; int base;
    if      (blk < 256)  { src = a; dst = da; base = blk; }
    else if (blk < 1280) { src = b; dst = db; base = blk - 256; }
    else                 { src = c; dst = dc; base = blk - 1280; }
    cvt16(src, dst, (base * 256 + threadIdx.x) * 16);
}

__global__ void wcat_k(const float* __restrict__ v_w, const float* __restrict__ v_b,
                       const float* __restrict__ qmod_w, const float* __restrict__ qmod_b,
                       const float* __restrict__ kmod_w, const float* __restrict__ kmod_b,
                       const float* __restrict__ cq_w,   const float* __restrict__ ck_w,
                       __half* __restrict__ wcat, float* __restrict__ bcat)
{
    int idx = blockIdx.x * 256 + threadIdx.x;          // over 1024*1408
    int k = idx / VPW, n = idx - k * VPW;
    float v = 0.f;
    if      (n < 1024) v = v_w[k*1024 + n];
    else {
        int c = n - 1024;
        if      (c < 16)  v = qmod_w[k*Hh + c];
        else if (c < 32)  v = kmod_w[k*Hh + (c - 16)];
        else if (c < 160) v = cq_w[k*(Hh*CRc) + (c - 32)];
        else if (c < 288) v = ck_w[k*(Hh*CRc) + (c - 160)];
    }
    wcat[idx] = __float2half_rn(v);
    if (idx < VPW) {
        float bv = 0.f;
        if (idx < 1024) bv = v_b[idx];
        else { int p = idx - 1024; if (p < 16) bv = qmod_b[p]; else if (p < 32) bv = kmod_b[p - 16]; }
        bcat[idx] = bv;
    }
}

// ---------------- pooled mean over S ----------------
__global__ void pool1_k(const float* __restrict__ x, float* __restrict__ pp)
{
    int idx = blockIdx.x * 256 + threadIdx.x;
    int sl  = blockIdx.y;                           // 0..63
    int b = idx >> 10, d = idx & 1023;
    const float* xp = x + (size_t)(b*Ss + sl*16)*Dd + d;
    float s0=0,s1=0;
    #pragma unroll
    for (int q = 0; q < 16; q += 2) {
        s0 += xp[(size_t)(q+0)*Dd];
        s1 += xp[(size_t)(q+1)*Dd];
    }
    pp[sl*2048 + idx] = s0+s1;
}

__global__ void pool2_k(const float* __restrict__ pp, float* __restrict__ pooled)
{
    int idx = blockIdx.x * 256 + threadIdx.x;
    float s = 0.f;
    #pragma unroll
    for (int q = 0; q < 64; q++) s += pp[q*2048 + idx];
    pooled[idx] = s * (1.f/Ss);
}

// ---------------- gating ----------------
__global__ void __launch_bounds__(256) gating_k(const float* __restrict__ pooled,
    const float* __restrict__ gate_w, const float* __restrict__ gate_b,
    const float* __restrict__ mod_w,  const float* __restrict__ mod_b,
    const float* __restrict__ mod_basis, float* __restrict__ wts)
{
    int blk = blockIdx.x;
    int b = blk / Hh, h = blk % Hh;
    int tid = threadIdx.x, warp = tid >> 5, lane = tid & 31;
    __shared__ float ps[Dd];
    __shared__ float outs[24];
    __shared__ float gls[MMm];
    for (int q = tid; q < Dd; q += 256) ps[q] = pooled[b*Dd + q];
    __syncthreads();
    for (int o = warp; o < 24; o += 8) {
        const float* wcol; int stride; float bias;
        if (o < 16) { wcol = gate_w + h*MMm + o;      stride = Hh*MMm; bias = gate_b[h*MMm + o]; }
        else        { int r = o-16; wcol = mod_w + h*RMm + r; stride = Hh*RMm; bias = mod_b[h*RMm + r]; }
        float s = 0.f;
        for (int dI = lane; dI < Dd; dI += 32) s += ps[dI] * wcol[(size_t)dI * stride];
        #pragma unroll
        for (int off = 16; off; off >>= 1) s += __shfl_xor_sync(0xffffffffu, s, off);
        if (lane == 0) outs[o] = s + bias;
    }
    __syncthreads();
    if (tid < MMm) {
        float gl = outs[tid];
        #pragma unroll
        for (int r = 0; r < RMm; r++) gl += outs[16 + r] * mod_basis[(r*Hh + h)*MMm + tid];
        gls[tid] = gl;
    }
    __syncthreads();
    if (tid == 0) {
        float mx = -1e30f;
        for (int m = 0; m < MMm; m++) mx = fmaxf(mx, gls[m]);
        float e[MMm], sm = 0.f;
        for (int m = 0; m < MMm; m++) { e[m] = expf(gls[m] - mx); sm += e[m]; }
        float inv = 1.f / sm;
        for (int m = 0; m < MMm; m++) wts[(b*Hh + h)*MMm + m] = e[m] * inv;
    }
}

// ---------------- wave mask -> causal Toeplitz row ----------------
__global__ void __launch_bounds__(256) wave_k(const float* __restrict__ wts,
    const float* __restrict__ freqs, const float* __restrict__ amps,
    const float* __restrict__ phases, float* __restrict__ ckr)
{
    int b = blockIdx.z, h = blockIdx.y;
    int d = blockIdx.x * 256 + threadIdx.x;
    __shared__ float fs[MMm*WWw*2], as_[MMm*WWw], ph_[MMm*WWw], ws[MMm];
    int t = threadIdx.x;
    fs[t] = freqs[h*MMm*WWw*2 + t];
    if (t < MMm*WWw) { as_[t] = amps[h*MMm*WWw + t]; ph_[t] = phases[h*MMm*WWw + t]; }
    if (t < MMm) ws[t] = wts[(b*Hh + h)*MMm + t];
    __syncthreads();
    float p1 = d * (1.f/Ss);
    float p2 = (d == 0) ? 0.f : sqrtf((float)d + 1e-6f) * 0.03125f;
    float kern = 0.f;
    #pragma unroll
    for (int m = 0; m < MMm; m++) {
        float acc = 0.f;
        #pragma unroll
        for (int w = 0; w < WWw; w++) {
            int iw = m*WWw + w;
            acc += as_[iw] * sinf(fs[iw*2+0]*p1 + fs[iw*2+1]*p2 + ph_[iw]);
        }
        kern += ws[m] * acc;
    }
    float dens = 1.f / (1.f + expf(-6.f * kern));
    float win  = expf(-(float)d * (float)d * (1.f/131072.f));
    ckr[(b*Hh + h)*Ss + d] = 3.f * dens * win;
}

// ---------------- flash attention, tensor-core PV, 128 queries/CTA ----------------
__global__ void __launch_bounds__(256) attn_k(const __half* __restrict__ vp,
    const float* __restrict__ ckr, __half* __restrict__ ctx)
{
    const int b = blockIdx.z, h = blockIdx.y;
    const int qb = (gridDim.x - 1 - blockIdx.x) * 128;     // big tiles first
    const int tid = threadIdx.x, warp = tid >> 5, lane = tid & 31;
    const int g = lane >> 2, c2 = (lane & 3) * 2;

    __shared__ float  ck_s[Ss];
    __shared__ __align__(16) __half vts[64 * 68];
    __shared__ __align__(16) __half kcs[64 * 18];

    for (int o = tid; o < Ss; o += 256) ck_s[o] = ckr[(b*Hh + h)*Ss + o];

    const __half* vpB = vp + (size_t)(b*Ss) * VPW;
    const float cmix = 0.0530330085889911f;

    const int i_lo = qb + warp*16 + g, i_hi = i_lo + 8;
    uint32_t aq[4];
    {
        float qlo0 = cmix * __half2float(vpB[(size_t)i_lo*VPW + 1056 + h*CRc + c2]);
        float qlo1 = cmix * __half2float(vpB[(size_t)i_lo*VPW + 1056 + h*CRc + c2 + 1]);
        float qhi0 = cmix * __half2float(vpB[(size_t)i_hi*VPW + 1056 + h*CRc + c2]);
        float qhi1 = cmix * __half2float(vpB[(size_t)i_hi*VPW + 1056 + h*CRc + c2 + 1]);
        aq[0] = h2u(qlo0, qlo1);
        aq[1] = h2u(qhi0, qhi1);
        if ((lane & 3) == 0) {
            aq[2] = h2u(1.f, __half2float(vpB[(size_t)i_lo*VPW + 1024 + h]));
            aq[3] = h2u(1.f, __half2float(vpB[(size_t)i_hi*VPW + 1024 + h]));
        } else { aq[2] = 0; aq[3] = 0; }
    }

    float m_lo = -1e30f, m_hi = -1e30f, l_lo = 0.f, l_hi = 0.f;
    float o_[8][4];
    #pragma unroll
    for (int nt = 0; nt < 8; nt++)
        #pragma unroll
        for (int q = 0; q < 4; q++) o_[nt][q] = 0.f;

    const int iwmax = qb + warp*16 + 15;

    for (int jb = 0; jb <= qb + 64; jb += 64) {
        __syncthreads();
        if (tid < 128) {
            int j = tid >> 1, sub = tid & 1;
            uint32_t* dst = (uint32_t*)((char*)kcs + j*36 + sub*16);
            if (sub == 0) {
                const __half* kc = vpB + (size_t)(jb + j)*VPW + 1184 + h*CRc;
                dst[0] = *(const uint32_t*)(kc);
                dst[1] = *(const uint32_t*)(kc + 2);
                dst[2] = *(const uint32_t*)(kc + 4);
                dst[3] = *(const uint32_t*)(kc + 6);
            } else {
                float km = __half2float(vpB[(size_t)(jb + j)*VPW + 1040 + h]);
                dst[0] = h2u(km, 1.f); dst[1] = 0; dst[2] = 0; dst[3] = 0;
            }
        }
        #pragma unroll 4
        for (int it = 0; it < 16; it++) {
            int idx = it * 256 + tid;
            int j = idx >> 6, d = idx & 63;
            vts[d*68 + j] = vpB[(size_t)(jb + j)*VPW + h*HDd + d];
        }
        __syncthreads();

        if (jb <= iwmax) {
            float s[8][4];
            #pragma unroll
            for (int nt = 0; nt < 8; nt++) {
                s[nt][0] = s[nt][1] = s[nt][2] = s[nt][3] = 0.f;
                uint32_t kb[2];
                const char* base = (const char*)kcs + (nt*8 + g)*36 + (lane & 3)*4;
                kb[0] = *(const uint32_t*)(base);
                kb[1] = *(const uint32_t*)(base + 16);
                mma_f16(s[nt], aq, kb);
            }
            const int irl = i_lo - jb, irh = irl + 8;
            const bool mlo = (irl < 63), mhi = (irh < 63);
            #pragma unroll
            for (int nt = 0; nt < 8; nt++) {
                int j0 = nt*8 + c2;
                if (!mlo) {
                    s[nt][0] += ck_s[irl - j0];
                    s[nt][1] += ck_s[irl - j0 - 1];
                } else {
                    s[nt][0] = (j0     <= irl) ? s[nt][0] + ck_s[irl - j0]     : -1e30f;
                    s[nt][1] = (j0 + 1 <= irl) ? s[nt][1] + ck_s[irl - j0 - 1] : -1e30f;
                }
                if (!mhi) {
                    s[nt][2] += ck_s[irh - j0];
                    s[nt][3] += ck_s[irh - j0 - 1];
                } else {
                    s[nt][2] = (j0     <= irh) ? s[nt][2] + ck_s[irh - j0]     : -1e30f;
                    s[nt][3] = (j0 + 1 <= irh) ? s[nt][3] + ck_s[irh - j0 - 1] : -1e30f;
                }
            }
            float mx_lo = -1e30f, mx_hi = -1e30f;
            #pragma unroll
            for (int nt = 0; nt < 8; nt++) {
                mx_lo = fmaxf(mx_lo, fmaxf(s[nt][0], s[nt][1]));
                mx_hi = fmaxf(mx_hi, fmaxf(s[nt][2], s[nt][3]));
            }
            mx_lo = fmaxf(mx_lo, __shfl_xor_sync(0xffffffffu, mx_lo, 1));
            mx_lo = fmaxf(mx_lo, __shfl_xor_sync(0xffffffffu, mx_lo, 2));
            mx_hi = fmaxf(mx_hi, __shfl_xor_sync(0xffffffffu, mx_hi, 1));
            mx_hi = fmaxf(mx_hi, __shfl_xor_sync(0xffffffffu, mx_hi, 2));
            float mn_lo = fmaxf(m_lo, mx_lo), mn_hi = fmaxf(m_hi, mx_hi);
            float sc_lo = __expf(m_lo - mn_lo), sc_hi = __expf(m_hi - mn_hi);
            float p[8][4], sum_lo = 0.f, sum_hi = 0.f;
            #pragma unroll
            for (int nt = 0; nt < 8; nt++) {
                p[nt][0] = __expf(s[nt][0] - mn_lo);
                p[nt][1] = __expf(s[nt][1] - mn_lo);
                p[nt][2] = __expf(s[nt][2] - mn_hi);
                p[nt][3] = __expf(s[nt][3] - mn_hi);
                sum_lo += p[nt][0] + p[nt][1];
                sum_hi += p[nt][2] + p[nt][3];
            }
            sum_lo += __shfl_xor_sync(0xffffffffu, sum_lo, 1);
            sum_lo += __shfl_xor_sync(0xffffffffu, sum_lo, 2);
            sum_hi += __shfl_xor_sync(0xffffffffu, sum_hi, 1);
            sum_hi += __shfl_xor_sync(0xffffffffu, sum_hi, 2);
            l_lo = l_lo * sc_lo + sum_lo;  m_lo = mn_lo;
            l_hi = l_hi * sc_hi + sum_hi;  m_hi = mn_hi;
            #pragma unroll
            for (int nt = 0; nt < 8; nt++) {
                o_[nt][0] *= sc_lo; o_[nt][1] *= sc_lo;
                o_[nt][2] *= sc_hi; o_[nt][3] *= sc_hi;
            }
            #pragma unroll
            for (int kt = 0; kt < 4; kt++) {
                uint32_t pa[4];
                pa[0] = h2u(p[2*kt][0],   p[2*kt][1]);
                pa[1] = h2u(p[2*kt][2],   p[2*kt][3]);
                pa[2] = h2u(p[2*kt+1][0], p[2*kt+1][1]);
                pa[3] = h2u(p[2*kt+1][2], p[2*kt+1][3]);
                #pragma unroll
                for (int nt = 0; nt < 8; nt++) {
                    uint32_t vb[2];
                    const char* base = (const char*)vts + ((nt*8 + g)*68 + kt*16 + c2)*2;
                    vb[0] = *(const uint32_t*)(base);
                    vb[1] = *(const uint32_t*)(base + 16);
                    mma_f16(o_[nt], pa, vb);
                }
            }
        }
    }

    float inv_lo = 1.f / l_lo, inv_hi = 1.f / l_hi;
    #pragma unroll
    for (int nt = 0; nt < 8; nt++) {
        __half2* plo = (__half2*)(ctx + (size_t)(b*Ss + i_lo)*Dd + h*HDd + nt*8 + c2);
        __half2* phi = (__half2*)(ctx + (size_t)(b*Ss + i_hi)*Dd + h*HDd + nt*8 + c2);
        *plo = __floats2half2_rn(o_[nt][0]*inv_lo, o_[nt][1]*inv_lo);
        *phi = __floats2half2_rn(o_[nt][2]*inv_hi, o_[nt][3]*inv_hi);
    }
}

// ---------------- fused residual + LayerNorm ----------------
__global__ void __launch_bounds__(256) ln_k(const float* __restrict__ a,
    const float* __restrict__ r, const float* __restrict__ g,
    const float* __restrict__ bta, float* __restrict__ out, __half* __restrict__ out2)
{
    int row = blockIdx.x;
    size_t base = (size_t)row * Dd;
    int tid = threadIdx.x;
    float vals[4], s = 0.f, s2 = 0.f;
    #pragma unroll
    for (int q = 0; q < 4; q++) {
        int idx = tid + q*256;
        float xv = a[base + idx] + r[base + idx];
        vals[q] = xv; s += xv; s2 += xv*xv;
    }
    __shared__ float red[64];
    #pragma unroll
    for (int o = 16; o; o >>= 1) {
        s  += __shfl_xor_sync(0xffffffffu, s,  o);
        s2 += __shfl_xor_sync(0xffffffffu, s2, o);
    }
    int warp = tid >> 5, lane = tid & 31;
    if (lane == 0) { red[warp] = s; red[32 + warp] = s2; }
    __syncthreads();
    if (warp == 0) {
        float a1 = (lane < 8) ? red[lane] : 0.f;
        float a2 = (lane < 8) ? red[32 + lane] : 0.f;
        #pragma unroll
        for (int o = 4; o; o >>= 1) {
            a1 += __shfl_xor_sync(0xffffffffu, a1, o);
            a2 += __shfl_xor_sync(0xffffffffu, a2, o);
        }
        if (lane == 0) { red[0] = a1; red[1] = a2; }
    }
    __syncthreads();
    float mean = red[0] * (1.f/Dd);
    float var  = red[1] * (1.f/Dd) - mean*mean;
    float rstd = rsqrtf(var + 1e-5f);
    #pragma unroll
    for (int q = 0; q < 4; q++) {
        int idx = tid + q*256;
        float o = (vals[q] - mean) * rstd * g[idx] + bta[idx];
        out[base + idx] = o;
        if (out2) out2[base + idx] = __float2half_rn(o);
    }
}

// ---------------- launch ----------------
extern "C" void kernel_launch(void* const* d_in, const int* in_sizes, int n_in,
                              void* d_out, int out_size)
{
    const float* x      = (const float*)d_in[0];
    const float* v_w    = (const float*)d_in[1];
    const float* v_b    = (const float*)d_in[2];
    const float* out_w  = (const float*)d_in[3];
    const float* out_b  = (const float*)d_in[4];
    const float* qmod_w = (const float*)d_in[5];
    const float* qmod_b = (const float*)d_in[6];
    const float* kmod_w = (const float*)d_in[7];
    const float* kmod_b = (const float*)d_in[8];
    const float* gate_w = (const float*)d_in[9];
    const float* gate_b = (const float*)d_in[10];
    const float* mod_w  = (const float*)d_in[11];
    const float* mod_b  = (const float*)d_in[12];
    const float* mod_basis = (const float*)d_in[13];
    const float* freqs  = (const float*)d_in[14];
    const float* amps   = (const float*)d_in[15];
    const float* phases = (const float*)d_in[16];
    const float* cq_w   = (const float*)d_in[17];
    const float* ck_w   = (const float*)d_in[18];
    const float* ffn_w1 = (const float*)d_in[19];
    const float* ffn_b1 = (const float*)d_in[20];
    const float* ffn_w2 = (const float*)d_in[21];
    const float* ffn_b2 = (const float*)d_in[22];
    const float* ln1_g  = (const float*)d_in[23];
    const float* ln1_b  = (const float*)d_in[24];
    const float* ln2_g  = (const float*)d_in[25];
    const float* ln2_b  = (const float*)d_in[26];
    float* out = (float*)d_out;

    __half *pxh, *pwcat, *pvph, *powh, *pw1h, *pw2h, *pctxh, *phch, *pffnh;
    float *pbcat, *ppp, *ppool, *pwts, *pck, *pao, *ph, *pf2;
    cudaGetSymbolAddress((void**)&pxh,  g_xh);
    cudaGetSymbolAddress((void**)&pwcat,g_wcat);
    cudaGetSymbolAddress((void**)&pbcat,g_bcat);
    cudaGetSymbolAddress((void**)&pvph, g_vph);
    cudaGetSymbolAddress((void**)&powh, g_owh);
    cudaGetSymbolAddress((void**)&pw1h, g_w1h);
    cudaGetSymbolAddress((void**)&pw2h, g_w2h);
    cudaGetSymbolAddress((void**)&pctxh,g_ctxh);
    cudaGetSymbolAddress((void**)&phch, g_hch);
    cudaGetSymbolAddress((void**)&pffnh,g_ffnh);
    cudaGetSymbolAddress((void**)&ppp,  g_pp);
    cudaGetSymbolAddress((void**)&ppool,g_pool);
    cudaGetSymbolAddress((void**)&pwts, g_wts);
    cudaGetSymbolAddress((void**)&pck,  g_ckr);
    cudaGetSymbolAddress((void**)&pao,  g_ao);
    cudaGetSymbolAddress((void**)&ph,   g_h);
    cudaGetSymbolAddress((void**)&pf2,  g_f2);

    cudaFuncSetAttribute(gemmh<2,false,__half>, cudaFuncAttributeMaxDynamicSharedMemorySize, 73728);
    cudaFuncSetAttribute(gemmh<2,false,float>,  cudaFuncAttributeMaxDynamicSharedMemorySize, 73728);
    cudaFuncSetAttribute(gemmh<4,true,__half>,  cudaFuncAttributeMaxDynamicSharedMemorySize, 98304);

    // fork two side streams inside the capture (kernels + events only)
    cudaStream_t s1, s2;
    cudaStreamCreateWithFlags(&s1, cudaStreamNonBlocking);
    cudaStreamCreateWithFlags(&s2, cudaStreamNonBlocking);
    cudaEvent_t e0, e1a, e1, e2;
    cudaEventCreateWithFlags(&e0,  cudaEventDisableTiming);
    cudaEventCreateWithFlags(&e1a, cudaEventDisableTiming);
    cudaEventCreateWithFlags(&e1,  cudaEventDisableTiming);
    cudaEventCreateWithFlags(&e2,  cudaEventDisableTiming);
    cudaEventRecord(e0, 0);
    cudaStreamWaitEvent(s1, e0, 0);
    cudaStreamWaitEvent(s2, e0, 0);

    // s1: fused-v weight pack (joined before vp GEMM), then FFN/out-proj conversions
    wcat_k<<<(Dd*VPW)/256, 256, 0, s1>>>(v_w, v_b, qmod_w, qmod_b, kmod_w, kmod_b, cq_w, ck_w, pwcat, pbcat);
    cudaEventRecord(e1a, s1);
    cvt3_k<<<2304, 256, 0, s1>>>(out_w, powh, ffn_w1, pw1h, ffn_w2, pw2h);
    cudaEventRecord(e1, s1);

    // s2: gating path (joined before attention)
    pool1_k<<<dim3(8,64), 256, 0, s2>>>(x, ppp);
    pool2_k<<<8, 256, 0, s2>>>(ppp, ppool);
    gating_k<<<Bb*Hh, 256, 0, s2>>>(ppool, gate_w, gate_b, mod_w, mod_b, mod_basis, pwts);
    wave_k<<<dim3(Ss/256, Hh, Bb), 256, 0, s2>>>(pwts, freqs, amps, phases, pck);
    cudaEventRecord(e2, s2);

    // s0: main chain
    cvth_k<<<(ROWS*Dd)/4096, 256>>>(x, pxh);
    cudaStreamWaitEvent(0, e1a, 0);  // join packed weights
    gemmh<2,false,__half><<<dim3(VPW/128, ROWS/64), 256, 73728>>>(pxh, pwcat, pbcat, pvph, ROWS, VPW, Dd, VPW);

    cudaStreamWaitEvent(0, e2, 0);   // join gating path
    attn_k<<<dim3(Ss/128, Hh, Bb), 256>>>(pvph, pck, pctxh);

    cudaStreamWaitEvent(0, e1, 0);   // join weight conversions
    gemmh<2,false,float><<<dim3(Dd/128, ROWS/64), 256, 73728>>>(pctxh, powh, out_b, pao, ROWS, Dd, Dd, Dd);

    ln_k<<<ROWS, 256>>>(x, pao, ln1_g, ln1_b, ph, phch);
    gemmh<4,true,__half><<<dim3(FFD/128, ROWS/128), 256, 98304>>>(phch,  pw1h, ffn_b1, pffnh, ROWS, FFD, Dd, FFD);
    gemmh<2,false,float><<<dim3(Dd/128, ROWS/64), 256, 73728>>>(pffnh, pw2h, ffn_b2, pf2,  ROWS, Dd, FFD, Dd);
    ln_k<<<ROWS, 256>>>(ph, pf2, ln2_g, ln2_b, out, nullptr);

    // side streams are joined (events waited on) — safe to release handles
    cudaEventDestroy(e0);
    cudaEventDestroy(e1a);
    cudaEventDestroy(e1);
    cudaEventDestroy(e2);
    cudaStreamDestroy(s1);
    cudaStreamDestroy(s2);
}

// round 13
// speedup vs baseline: 1.1487x; 1.1487x over previous
#include <cuda_runtime.h>
#include <cuda_fp16.h>
#include <math.h>
#include <stdint.h>

// ---------------- problem constants ----------------
#define Bb   2
#define Ss   1024
#define Dd   1024
#define Hh   16
#define HDd  64
#define MMm  16
#define WWw  8
#define RMm  8
#define CRc  8
#define FFD  4096
#define ROWS (Bb*Ss)          // 2048
#define VPW  1408             // v(1024) | qm(16) km(16) qc(128) kc(128) pad

// ---------------- scratch ----------------
__device__ __half g_xh   [ROWS*Dd];
__device__ __half g_wcat [Dd*VPW];
__device__ float  g_bcat [VPW];
__device__ __half g_vph  [ROWS*VPW];
__device__ __half g_owh  [Dd*Dd];
__device__ __half g_w1h  [Dd*FFD];
__device__ __half g_w2h  [FFD*Dd];
__device__ __half g_ctxh [ROWS*Dd];
__device__ __half g_hch  [ROWS*Dd];
__device__ __half g_ffnh [ROWS*FFD];
__device__ float  g_pp   [64*2048];
__device__ float  g_pool [Bb*Dd];
__device__ float  g_wts  [Bb*Hh*MMm];
__device__ float  g_ckr  [Bb*Hh*Ss];
__device__ float  g_ao   [ROWS*Dd];
__device__ float  g_h    [ROWS*Dd];
__device__ float  g_f2   [ROWS*Dd];

// ---------------- helpers ----------------
__device__ __forceinline__ uint32_t smem_u32(const void* p) {
    uint32_t a;
    asm("{ .reg .u64 t; cvta.to.shared.u64 t, %1; cvt.u32.u64 %0, t; }" : "=r"(a) : "l"(p));
    return a;
}
__device__ __forceinline__ void mma_f16(float* c, const uint32_t* a, const uint32_t* b) {
    asm volatile(
        "mma.sync.aligned.m16n8k16.row.col.f32.f16.f16.f32 "
        "{%0,%1,%2,%3}, {%4,%5,%6,%7}, {%8,%9}, {%0,%1,%2,%3};"
        : "+f"(c[0]), "+f"(c[1]), "+f"(c[2]), "+f"(c[3])
        : "r"(a[0]), "r"(a[1]), "r"(a[2]), "r"(a[3]), "r"(b[0]), "r"(b[1]));
}
__device__ __forceinline__ void cpa16(uint32_t dst, const void* src) {
    asm volatile("cp.async.cg.shared.global [%0], [%1], 16;" :: "r"(dst), "l"(src));
}
#define CPA_COMMIT() asm volatile("cp.async.commit_group;" ::: "memory")
__device__ __forceinline__ uint32_t h2u(float a, float b) {
    __half2 h = __floats2half2_rn(a, b);
    return *(uint32_t*)&h;
}
__device__ __forceinline__ void st2(float* p, float a, float b) { *(float2*)p = make_float2(a, b); }
__device__ __forceinline__ void st2(__half* p, float a, float b) { *(__half2*)p = __floats2half2_rn(a, b); }

// ---------------- fp16 GEMM: C[M,0..N) = A[M,K] @ B[K,N] + bias ----------------
// A half K-major; B half row-major [K][N] (stride N). C row stride ldc.
// CTA tile 128x128, K-tile 64, 3-stage cp.async pipeline (32 KB/stage).
template<bool GELU, typename OT>
__global__ void __launch_bounds__(256, 2)
gemmh(const __half* __restrict__ A, const __half* __restrict__ B,
      const float* __restrict__ bias, OT* __restrict__ C,
      int M, int N, int K, int ldc)
{
    extern __shared__ __align__(16) unsigned char smem[];
    const int tid = threadIdx.x, lane = tid & 31, warp = tid >> 5;
    const int wm = warp & 1, wn = warp >> 1;       // warp tile 64x32
    const int rr = lane >> 2, cl = lane & 3;
    const int m0 = blockIdx.y * 128, n0 = blockIdx.x * 128;
    const __half* Arow = A + (size_t)m0 * K;
    const __half* Bcol = B + n0;
    const uint32_t sbase = smem_u32(smem);
    const int T = K >> 6;

    float acc[4][4][4];
    #pragma unroll
    for (int mt = 0; mt < 4; mt++)
        #pragma unroll
        for (int nt = 0; nt < 4; nt++)
            #pragma unroll
            for (int q = 0; q < 4; q++) acc[mt][nt][q] = 0.f;

    auto stage = [&](int t) {
        if (t < T) {
            const uint32_t sb = sbase + (t % 3) * 32768;
            const int k0 = t << 6;
            #pragma unroll
            for (int q = 0; q < 4; q++) {
                int ch = q * 256 + tid;
                int row = ch >> 3, u = ch & 7;
                uint32_t off = row * 128 + ((u ^ (row & 7)) << 4);
                cpa16(sb + off, Arow + (size_t)row * K + k0 + u * 8);
            }
            #pragma unroll
            for (int q = 0; q < 4; q++) {
                int ch = q * 256 + tid;
                int k = ch >> 4, u = ch & 15;
                uint32_t off = k * 256 + ((u ^ (k & 7)) << 4);
                cpa16(sb + 16384 + off, Bcol + (size_t)(k0 + k) * N + u * 8);
            }
        }
        CPA_COMMIT();
    };

    stage(0); stage(1);
    for (int t = 0; t < T; t++) {
        asm volatile("cp.async.wait_group 1;" ::: "memory");
        __syncthreads();
        stage(t + 2);
        const uint32_t sA = sbase + (t % 3) * 32768;
        const uint32_t sB = sA + 16384;

        #pragma unroll
        for (int kk = 0; kk < 4; kk++) {
            uint32_t af[4][4], bf[4][2];
            #pragma unroll
            for (int mt = 0; mt < 4; mt++) {
                int row = wm * 64 + mt * 16 + ((lane >> 3) & 1) * 8 + (lane & 7);
                int unit = kk * 2 + (lane >> 4);
                uint32_t addr = sA + row * 128 + ((unit ^ (row & 7)) << 4);
                asm volatile("ldmatrix.sync.aligned.m8n8.x4.shared.b16 {%0,%1,%2,%3}, [%4];"
                             : "=r"(af[mt][0]), "=r"(af[mt][1]), "=r"(af[mt][2]), "=r"(af[mt][3])
                             : "r"(addr));
            }
            #pragma unroll
            for (int nt = 0; nt < 4; nt += 2) {
                int rowk = kk * 16 + (lane & 15);
                int unitn = wn * 4 + nt + (lane >> 4);
                uint32_t addr = sB + rowk * 256 + ((unitn ^ (rowk & 7)) << 4);
                asm volatile("ldmatrix.sync.aligned.m8n8.x4.trans.shared.b16 {%0,%1,%2,%3}, [%4];"
                             : "=r"(bf[nt][0]), "=r"(bf[nt][1]), "=r"(bf[nt+1][0]), "=r"(bf[nt+1][1])
                             : "r"(addr));
            }
            #pragma unroll
            for (int mt = 0; mt < 4; mt++)
                #pragma unroll
                for (int nt = 0; nt < 4; nt++)
                    mma_f16(acc[mt][nt], af[mt], bf[nt]);
        }
    }

    #pragma unroll
    for (int mt = 0; mt < 4; mt++) {
        #pragma unroll
        for (int nt = 0; nt < 4; nt++) {
            int r  = m0 + wm * 64 + mt * 16 + rr;
            int cc = n0 + wn * 32 + nt * 8 + 2 * cl;
            float b0 = bias ? bias[cc]     : 0.f;
            float b1 = bias ? bias[cc + 1] : 0.f;
            float v0 = acc[mt][nt][0] + b0;
            float v1 = acc[mt][nt][1] + b1;
            float v2 = acc[mt][nt][2] + b0;
            float v3 = acc[mt][nt][3] + b1;
            if (GELU) {
                v0 = 0.5f * v0 * (1.f + erff(v0 * 0.70710678118654752f));
                v1 = 0.5f * v1 * (1.f + erff(v1 * 0.70710678118654752f));
                v2 = 0.5f * v2 * (1.f + erff(v2 * 0.70710678118654752f));
                v3 = 0.5f * v3 * (1.f + erff(v3 * 0.70710678118654752f));
            }
            st2(C + (size_t)r * ldc + cc,       v0, v1);
            st2(C + (size_t)(r + 8) * ldc + cc, v2, v3);
        }
    }
}

// ---------------- prep kernels ----------------
__device__ __forceinline__ void cvt16(const float* __restrict__ src, __half* __restrict__ dst, int i)
{
    float4 v0 = *(const float4*)(src + i);
    float4 v1 = *(const float4*)(src + i + 4);
    float4 v2 = *(const float4*)(src + i + 8);
    float4 v3 = *(const float4*)(src + i + 12);
    uint4 o0, o1;
    o0.x = h2u(v0.x, v0.y); o0.y = h2u(v0.z, v0.w);
    o0.z = h2u(v1.x, v1.y); o0.w = h2u(v1.z, v1.w);
    o1.x = h2u(v2.x, v2.y); o1.y = h2u(v2.z, v2.w);
    o1.z = h2u(v3.x, v3.y); o1.w = h2u(v3.z, v3.w);
    *(uint4*)(dst + i)     = o0;
    *(uint4*)(dst + i + 8) = o1;
}

__global__ void cvth_k(const float* __restrict__ src, __half* __restrict__ dst)
{
    cvt16(src, dst, (blockIdx.x * 256 + threadIdx.x) * 16);
}

__global__ void cvt3_k(const float* __restrict__ a, __half* __restrict__ da,
                       const float* __restrict__ b, __half* __restrict__ db,
                       const float* __restrict__ c, __half* __restrict__ dc)
{
    int blk = blockIdx.x;
    const float* src; __half* dst; int base;
    if      (blk < 256)  { src = a; dst = da; base = blk; }
    else if (blk < 1280) { src = b; dst = db; base = blk - 256; }
    else                 { src = c; dst = dc; base = blk - 1280; }
    cvt16(src, dst, (base * 256 + threadIdx.x) * 16);
}

__global__ void wcat_k(const float* __restrict__ v_w, const float* __restrict__ v_b,
                       const float* __restrict__ qmod_w, const float* __restrict__ qmod_b,
                       const float* __restrict__ kmod_w, const float* __restrict__ kmod_b,
                       const float* __restrict__ cq_w,   const float* __restrict__ ck_w,
                       __half* __restrict__ wcat, float* __restrict__ bcat)
{
    int idx = blockIdx.x * 256 + threadIdx.x;          // over 1024*1408
    int k = idx / VPW, n = idx - k * VPW;
    float v = 0.f;
    if      (n < 1024) v = v_w[k*1024 + n];
    else {
        int c = n - 1024;
        if      (c < 16)  v = qmod_w[k*Hh + c];
        else if (c < 32)  v = kmod_w[k*Hh + (c - 16)];
        else if (c < 160) v = cq_w[k*(Hh*CRc) + (c - 32)];
        else if (c < 288) v = ck_w[k*(Hh*CRc) + (c - 160)];
    }
    wcat[idx] = __float2half_rn(v);
    if (idx < VPW) {
        float bv = 0.f;
        if (idx < 1024) bv = v_b[idx];
        else { int p = idx - 1024; if (p < 16) bv = qmod_b[p]; else if (p < 32) bv = kmod_b[p - 16]; }
        bcat[idx] = bv;
    }
}

// ---------------- pooled mean over S ----------------
__global__ void pool1_k(const float* __restrict__ x, float* __restrict__ pp)
{
    int idx = blockIdx.x * 256 + threadIdx.x;
    int sl  = blockIdx.y;                           // 0..63
    int b = idx >> 10, d = idx & 1023;
    const float* xp = x + (size_t)(b*Ss + sl*16)*Dd + d;
    float s0=0,s1=0;
    #pragma unroll
    for (int q = 0; q < 16; q += 2) {
        s0 += xp[(size_t)(q+0)*Dd];
        s1 += xp[(size_t)(q+1)*Dd];
    }
    pp[sl*2048 + idx] = s0+s1;
}

__global__ void pool2_k(const float* __restrict__ pp, float* __restrict__ pooled)
{
    int idx = blockIdx.x * 256 + threadIdx.x;
    float s = 0.f;
    #pragma unroll
    for (int q = 0; q < 64; q++) s += pp[q*2048 + idx];
    pooled[idx] = s * (1.f/Ss);
}

// ---------------- gating ----------------
__global__ void __launch_bounds__(256) gating_k(const float* __restrict__ pooled,
    const float* __restrict__ gate_w, const float* __restrict__ gate_b,
    const float* __restrict__ mod_w,  const float* __restrict__ mod_b,
    const float* __restrict__ mod_basis, float* __restrict__ wts)
{
    int blk = blockIdx.x;
    int b = blk / Hh, h = blk % Hh;
    int tid = threadIdx.x, warp = tid >> 5, lane = tid & 31;
    __shared__ float ps[Dd];
    __shared__ float outs[24];
    __shared__ float gls[MMm];
    for (int q = tid; q < Dd; q += 256) ps[q] = pooled[b*Dd + q];
    __syncthreads();
    for (int o = warp; o < 24; o += 8) {
        const float* wcol; int stride; float bias;
        if (o < 16) { wcol = gate_w + h*MMm + o;      stride = Hh*MMm; bias = gate_b[h*MMm + o]; }
        else        { int r = o-16; wcol = mod_w + h*RMm + r; stride = Hh*RMm; bias = mod_b[h*RMm + r]; }
        float s = 0.f;
        for (int dI = lane; dI < Dd; dI += 32) s += ps[dI] * wcol[(size_t)dI * stride];
        #pragma unroll
        for (int off = 16; off; off >>= 1) s += __shfl_xor_sync(0xffffffffu, s, off);
        if (lane == 0) outs[o] = s + bias;
    }
    __syncthreads();
    if (tid < MMm) {
        float gl = outs[tid];
        #pragma unroll
        for (int r = 0; r < RMm; r++) gl += outs[16 + r] * mod_basis[(r*Hh + h)*MMm + tid];
        gls[tid] = gl;
    }
    __syncthreads();
    if (tid == 0) {
        float mx = -1e30f;
        for (int m = 0; m < MMm; m++) mx = fmaxf(mx, gls[m]);
        float e[MMm], sm = 0.f;
        for (int m = 0; m < MMm; m++) { e[m] = expf(gls[m] - mx); sm += e[m]; }
        float inv = 1.f / sm;
        for (int m = 0; m < MMm; m++) wts[(b*Hh + h)*MMm + m] = e[m] * inv;
    }
}

// ---------------- wave mask -> causal Toeplitz row ----------------
__global__ void __launch_bounds__(256) wave_k(const float* __restrict__ wts,
    const float* __restrict__ freqs, const float* __restrict__ amps,
    const float* __restrict__ phases, float* __restrict__ ckr)
{
    int b = blockIdx.z, h = blockIdx.y;
    int d = blockIdx.x * 256 + threadIdx.x;
    __shared__ float fs[MMm*WWw*2], as_[MMm*WWw], ph_[MMm*WWw], ws[MMm];
    int t = threadIdx.x;
    fs[t] = freqs[h*MMm*WWw*2 + t];
    if (t < MMm*WWw) { as_[t] = amps[h*MMm*WWw + t]; ph_[t] = phases[h*MMm*WWw + t]; }
    if (t < MMm) ws[t] = wts[(b*Hh + h)*MMm + t];
    __syncthreads();
    float p1 = d * (1.f/Ss);
    float p2 = (d == 0) ? 0.f : sqrtf((float)d + 1e-6f) * 0.03125f;
    float kern = 0.f;
    #pragma unroll
    for (int m = 0; m < MMm; m++) {
        float acc = 0.f;
        #pragma unroll
        for (int w = 0; w < WWw; w++) {
            int iw = m*WWw + w;
            acc += as_[iw] * sinf(fs[iw*2+0]*p1 + fs[iw*2+1]*p2 + ph_[iw]);
        }
        kern += ws[m] * acc;
    }
    float dens = 1.f / (1.f + expf(-6.f * kern));
    float win  = expf(-(float)d * (float)d * (1.f/131072.f));
    ckr[(b*Hh + h)*Ss + d] = 3.f * dens * win;
}

// ---------------- flash attention, tensor-core PV, 128 queries/CTA ----------------
// V staged naturally [j][d] via double-buffered cp.async; PV B-frags via
// ldmatrix.x4.trans; km folded into registers from a once-per-CTA prefetch.
__global__ void __launch_bounds__(256) attn_k(const __half* __restrict__ vp,
    const float* __restrict__ ckr, __half* __restrict__ ctx)
{
    const int b = blockIdx.z, h = blockIdx.y;
    const int qb = (gridDim.x - 1 - blockIdx.x) * 128;     // big tiles first
    const int tid = threadIdx.x, warp = tid >> 5, lane = tid & 31;
    const int g = lane >> 2, c2 = (lane & 3) * 2;

    __shared__ float  ck_s[Ss];
    __shared__ __half km_s[Ss];
    __shared__ __align__(16) __half vsm[2][64*64];     // [j][d] 128B rows, swizzled
    __shared__ __align__(16) __half kcs[2][64*8];      // [j][8] 16B rows

    const __half* vpB = vp + (size_t)(b*Ss) * VPW;
    for (int o = tid; o < Ss; o += 256) {
        ck_s[o] = ckr[(b*Hh + h)*Ss + o];
        km_s[o] = vpB[(size_t)o*VPW + 1040 + h];
    }

    const float cmix = 0.0530330085889911f;
    const int i_lo = qb + warp*16 + g, i_hi = i_lo + 8;
    uint32_t aq[4];
    {
        float qlo0 = cmix * __half2float(vpB[(size_t)i_lo*VPW + 1056 + h*CRc + c2]);
        float qlo1 = cmix * __half2float(vpB[(size_t)i_lo*VPW + 1056 + h*CRc + c2 + 1]);
        float qhi0 = cmix * __half2float(vpB[(size_t)i_hi*VPW + 1056 + h*CRc + c2]);
        float qhi1 = cmix * __half2float(vpB[(size_t)i_hi*VPW + 1056 + h*CRc + c2 + 1]);
        aq[0] = h2u(qlo0, qlo1);
        aq[1] = h2u(qhi0, qhi1);
        if ((lane & 3) == 0) {
            aq[2] = h2u(1.f, __half2float(vpB[(size_t)i_lo*VPW + 1024 + h]));
            aq[3] = h2u(1.f, __half2float(vpB[(size_t)i_hi*VPW + 1024 + h]));
        } else { aq[2] = 0; aq[3] = 0; }
    }

    float m_lo = -1e30f, m_hi = -1e30f, l_lo = 0.f, l_hi = 0.f;
    float o_[8][4];
    #pragma unroll
    for (int nt = 0; nt < 8; nt++)
        #pragma unroll
        for (int q = 0; q < 4; q++) o_[nt][q] = 0.f;

    const int iwmax = qb + warp*16 + 15;
    const int nblk = qb/64 + 2;
    const uint32_t vbase = smem_u32(vsm);
    const uint32_t kbase = smem_u32(kcs);

    auto stage = [&](int t) {
        if (t < nblk) {
            const int jb = t * 64;
            const uint32_t vb = vbase + (t & 1) * 8192;
            const uint32_t kb = kbase + (t & 1) * 1024;
            #pragma unroll
            for (int q = 0; q < 2; q++) {
                int ch = q * 256 + tid;
                int j = ch >> 3, u = ch & 7;
                cpa16(vb + j*128 + ((u ^ (j & 7)) << 4),
                      vpB + (size_t)(jb + j)*VPW + h*HDd + u*8);
            }
            if (tid < 64)
                cpa16(kb + tid*16, vpB + (size_t)(jb + tid)*VPW + 1184 + h*CRc);
        }
        CPA_COMMIT();
    };

    stage(0);
    const __half one_h = __float2half_rn(1.f);
    for (int t = 0; t < nblk; t++) {
        const int jb = t * 64;
        stage(t + 1);
        asm volatile("cp.async.wait_group 1;" ::: "memory");
        __syncthreads();

        if (jb <= iwmax) {
            const uint32_t vb = vbase + (t & 1) * 8192;
            const __half* kcb = &kcs[t & 1][0];
            // scores: content mma + qm/km + Toeplitz
            float s[8][4];
            #pragma unroll
            for (int nt = 0; nt < 8; nt++) {
                s[nt][0] = s[nt][1] = s[nt][2] = s[nt][3] = 0.f;
                uint32_t kb2[2];
                kb2[0] = *(const uint32_t*)((const char*)(kcb + (nt*8 + g)*8) + (lane & 3)*4);
                if ((lane & 3) == 0) {
                    __half2 hh = __halves2half2(km_s[jb + nt*8 + g], one_h);
                    kb2[1] = *(uint32_t*)&hh;
                } else kb2[1] = 0;
                mma_f16(s[nt], aq, kb2);
            }
            const int irl = i_lo - jb, irh = irl + 8;
            const bool mlo = (irl < 63), mhi = (irh < 63);
            #pragma unroll
            for (int nt = 0; nt < 8; nt++) {
                int j0 = nt*8 + c2;
                if (!mlo) {
                    s[nt][0] += ck_s[irl - j0];
                    s[nt][1] += ck_s[irl - j0 - 1];
                } else {
                    s[nt][0] = (j0     <= irl) ? s[nt][0] + ck_s[irl - j0]     : -1e30f;
                    s[nt][1] = (j0 + 1 <= irl) ? s[nt][1] + ck_s[irl - j0 - 1] : -1e30f;
                }
                if (!mhi) {
                    s[nt][2] += ck_s[irh - j0];
                    s[nt][3] += ck_s[irh - j0 - 1];
                } else {
                    s[nt][2] = (j0     <= irh) ? s[nt][2] + ck_s[irh - j0]     : -1e30f;
                    s[nt][3] = (j0 + 1 <= irh) ? s[nt][3] + ck_s[irh - j0 - 1] : -1e30f;
                }
            }
            // online softmax (4-lane group reduce)
            float mx_lo = -1e30f, mx_hi = -1e30f;
            #pragma unroll
            for (int nt = 0; nt < 8; nt++) {
                mx_lo = fmaxf(mx_lo, fmaxf(s[nt][0], s[nt][1]));
                mx_hi = fmaxf(mx_hi, fmaxf(s[nt][2], s[nt][3]));
            }
            mx_lo = fmaxf(mx_lo, __shfl_xor_sync(0xffffffffu, mx_lo, 1));
            mx_lo = fmaxf(mx_lo, __shfl_xor_sync(0xffffffffu, mx_lo, 2));
            mx_hi = fmaxf(mx_hi, __shfl_xor_sync(0xffffffffu, mx_hi, 1));
            mx_hi = fmaxf(mx_hi, __shfl_xor_sync(0xffffffffu, mx_hi, 2));
            float mn_lo = fmaxf(m_lo, mx_lo), mn_hi = fmaxf(m_hi, mx_hi);
            float sc_lo = __expf(m_lo - mn_lo), sc_hi = __expf(m_hi - mn_hi);
            float p[8][4], sum_lo = 0.f, sum_hi = 0.f;
            #pragma unroll
            for (int nt = 0; nt < 8; nt++) {
                p[nt][0] = __expf(s[nt][0] - mn_lo);
                p[nt][1] = __expf(s[nt][1] - mn_lo);
                p[nt][2] = __expf(s[nt][2] - mn_hi);
                p[nt][3] = __expf(s[nt][3] - mn_hi);
                sum_lo += p[nt][0] + p[nt][1];
                sum_hi += p[nt][2] + p[nt][3];
            }
            sum_lo += __shfl_xor_sync(0xffffffffu, sum_lo, 1);
            sum_lo += __shfl_xor_sync(0xffffffffu, sum_lo, 2);
            sum_hi += __shfl_xor_sync(0xffffffffu, sum_hi, 1);
            sum_hi += __shfl_xor_sync(0xffffffffu, sum_hi, 2);
            l_lo = l_lo * sc_lo + sum_lo;  m_lo = mn_lo;
            l_hi = l_hi * sc_hi + sum_hi;  m_hi = mn_hi;
            #pragma unroll
            for (int nt = 0; nt < 8; nt++) {
                o_[nt][0] *= sc_lo; o_[nt][1] *= sc_lo;
                o_[nt][2] *= sc_hi; o_[nt][3] *= sc_hi;
            }
            // PV: P C-frags -> A-frags; V B-frags via ldmatrix.x4.trans
            #pragma unroll
            for (int kt = 0; kt < 4; kt++) {
                uint32_t pa[4];
                pa[0] = h2u(p[2*kt][0],   p[2*kt][1]);
                pa[1] = h2u(p[2*kt][2],   p[2*kt][3]);
                pa[2] = h2u(p[2*kt+1][0], p[2*kt+1][1]);
                pa[3] = h2u(p[2*kt+1][2], p[2*kt+1][3]);
                uint32_t bf[8][2];
                #pragma unroll
                for (int nt = 0; nt < 8; nt += 2) {
                    int row = kt*16 + (lane & 15);
                    int unit = nt + (lane >> 4);
                    uint32_t addr = vb + row*128 + ((unit ^ (row & 7)) << 4);
                    asm volatile("ldmatrix.sync.aligned.m8n8.x4.trans.shared.b16 {%0,%1,%2,%3}, [%4];"
                                 : "=r"(bf[nt][0]), "=r"(bf[nt][1]), "=r"(bf[nt+1][0]), "=r"(bf[nt+1][1])
                                 : "r"(addr));
                }
                #pragma unroll
                for (int nt = 0; nt < 8; nt++)
                    mma_f16(o_[nt], pa, bf[nt]);
            }
        }
        __syncthreads();
    }

    float inv_lo = 1.f / l_lo, inv_hi = 1.f / l_hi;
    #pragma unroll
    for (int nt = 0; nt < 8; nt++) {
        __half2* plo = (__half2*)(ctx + (size_t)(b*Ss + i_lo)*Dd + h*HDd + nt*8 + c2);
        __half2* phi = (__half2*)(ctx + (size_t)(b*Ss + i_hi)*Dd + h*HDd + nt*8 + c2);
        *plo = __floats2half2_rn(o_[nt][0]*inv_lo, o_[nt][1]*inv_lo);
        *phi = __floats2half2_rn(o_[nt][2]*inv_hi, o_[nt][3]*inv_hi);
    }
}

// ---------------- fused residual + LayerNorm ----------------
__global__ void __launch_bounds__(256) ln_k(const float* __restrict__ a,
    const float* __restrict__ r, const float* __restrict__ g,
    const float* __restrict__ bta, float* __restrict__ out, __half* __restrict__ out2)
{
    int row = blockIdx.x;
    size_t base = (size_t)row * Dd;
    int tid = threadIdx.x;
    float vals[4], s = 0.f, s2 = 0.f;
    #pragma unroll
    for (int q = 0; q < 4; q++) {
        int idx = tid + q*256;
        float xv = a[base + idx] + r[base + idx];
        vals[q] = xv; s += xv; s2 += xv*xv;
    }
    __shared__ float red[64];
    #pragma unroll
    for (int o = 16; o; o >>= 1) {
        s  += __shfl_xor_sync(0xffffffffu, s,  o);
        s2 += __shfl_xor_sync(0xffffffffu, s2, o);
    }
    int warp = tid >> 5, lane = tid & 31;
    if (lane == 0) { red[warp] = s; red[32 + warp] = s2; }
    __syncthreads();
    if (warp == 0) {
        float a1 = (lane < 8) ? red[lane] : 0.f;
        float a2 = (lane < 8) ? red[32 + lane] : 0.f;
        #pragma unroll
        for (int o = 4; o; o >>= 1) {
            a1 += __shfl_xor_sync(0xffffffffu, a1, o);
            a2 += __shfl_xor_sync(0xffffffffu, a2, o);
        }
        if (lane == 0) { red[0] = a1; red[1] = a2; }
    }
    __syncthreads();
    float mean = red[0] * (1.f/Dd);
    float var  = red[1] * (1.f/Dd) - mean*mean;
    float rstd = rsqrtf(var + 1e-5f);
    #pragma unroll
    for (int q = 0; q < 4; q++) {
        int idx = tid + q*256;
        float o = (vals[q] - mean) * rstd * g[idx] + bta[idx];
        out[base + idx] = o;
        if (out2) out2[base + idx] = __float2half_rn(o);
    }
}

// ---------------- launch ----------------
extern "C" void kernel_launch(void* const* d_in, const int* in_sizes, int n_in,
                              void* d_out, int out_size)
{
    const float* x      = (const float*)d_in[0];
    const float* v_w    = (const float*)d_in[1];
    const float* v_b    = (const float*)d_in[2];
    const float* out_w  = (const float*)d_in[3];
    const float* out_b  = (const float*)d_in[4];
    const float* qmod_w = (const float*)d_in[5];
    const float* qmod_b = (const float*)d_in[6];
    const float* kmod_w = (const float*)d_in[7];
    const float* kmod_b = (const float*)d_in[8];
    const float* gate_w = (const float*)d_in[9];
    const float* gate_b = (const float*)d_in[10];
    const float* mod_w  = (const float*)d_in[11];
    const float* mod_b  = (const float*)d_in[12];
    const float* mod_basis = (const float*)d_in[13];
    const float* freqs  = (const float*)d_in[14];
    const float* amps   = (const float*)d_in[15];
    const float* phases = (const float*)d_in[16];
    const float* cq_w   = (const float*)d_in[17];
    const float* ck_w   = (const float*)d_in[18];
    const float* ffn_w1 = (const float*)d_in[19];
    const float* ffn_b1 = (const float*)d_in[20];
    const float* ffn_w2 = (const float*)d_in[21];
    const float* ffn_b2 = (const float*)d_in[22];
    const float* ln1_g  = (const float*)d_in[23];
    const float* ln1_b  = (const float*)d_in[24];
    const float* ln2_g  = (const float*)d_in[25];
    const float* ln2_b  = (const float*)d_in[26];
    float* out = (float*)d_out;

    __half *pxh, *pwcat, *pvph, *powh, *pw1h, *pw2h, *pctxh, *phch, *pffnh;
    float *pbcat, *ppp, *ppool, *pwts, *pck, *pao, *ph, *pf2;
    cudaGetSymbolAddress((void**)&pxh,  g_xh);
    cudaGetSymbolAddress((void**)&pwcat,g_wcat);
    cudaGetSymbolAddress((void**)&pbcat,g_bcat);
    cudaGetSymbolAddress((void**)&pvph, g_vph);
    cudaGetSymbolAddress((void**)&powh, g_owh);
    cudaGetSymbolAddress((void**)&pw1h, g_w1h);
    cudaGetSymbolAddress((void**)&pw2h, g_w2h);
    cudaGetSymbolAddress((void**)&pctxh,g_ctxh);
    cudaGetSymbolAddress((void**)&phch, g_hch);
    cudaGetSymbolAddress((void**)&pffnh,g_ffnh);
    cudaGetSymbolAddress((void**)&ppp,  g_pp);
    cudaGetSymbolAddress((void**)&ppool,g_pool);
    cudaGetSymbolAddress((void**)&pwts, g_wts);
    cudaGetSymbolAddress((void**)&pck,  g_ckr);
    cudaGetSymbolAddress((void**)&pao,  g_ao);
    cudaGetSymbolAddress((void**)&ph,   g_h);
    cudaGetSymbolAddress((void**)&pf2,  g_f2);

    cudaFuncSetAttribute(gemmh<false,__half>, cudaFuncAttributeMaxDynamicSharedMemorySize, 98304);
    cudaFuncSetAttribute(gemmh<false,float>,  cudaFuncAttributeMaxDynamicSharedMemorySize, 98304);
    cudaFuncSetAttribute(gemmh<true,__half>,  cudaFuncAttributeMaxDynamicSharedMemorySize, 98304);

    // fork two side streams inside the capture (kernels + events only)
    cudaStream_t s1, s2;
    cudaStreamCreateWithFlags(&s1, cudaStreamNonBlocking);
    cudaStreamCreateWithFlags(&s2, cudaStreamNonBlocking);
    cudaEvent_t e0, e1a, e1, e2;
    cudaEventCreateWithFlags(&e0,  cudaEventDisableTiming);
    cudaEventCreateWithFlags(&e1a, cudaEventDisableTiming);
    cudaEventCreateWithFlags(&e1,  cudaEventDisableTiming);
    cudaEventCreateWithFlags(&e2,  cudaEventDisableTiming);
    cudaEventRecord(e0, 0);
    cudaStreamWaitEvent(s1, e0, 0);
    cudaStreamWaitEvent(s2, e0, 0);

    // s1: fused-v weight pack (joined before vp GEMM), then FFN/out-proj conversions
    wcat_k<<<(Dd*VPW)/256, 256, 0, s1>>>(v_w, v_b, qmod_w, qmod_b, kmod_w, kmod_b, cq_w, ck_w, pwcat, pbcat);
    cudaEventRecord(e1a, s1);
    cvt3_k<<<2304, 256, 0, s1>>>(out_w, powh, ffn_w1, pw1h, ffn_w2, pw2h);
    cudaEventRecord(e1, s1);

    // s2: gating path (joined before attention)
    pool1_k<<<dim3(8,64), 256, 0, s2>>>(x, ppp);
    pool2_k<<<8, 256, 0, s2>>>(ppp, ppool);
    gating_k<<<Bb*Hh, 256, 0, s2>>>(ppool, gate_w, gate_b, mod_w, mod_b, mod_basis, pwts);
    wave_k<<<dim3(Ss/256, Hh, Bb), 256, 0, s2>>>(pwts, freqs, amps, phases, pck);
    cudaEventRecord(e2, s2);

    // s0: main chain
    cvth_k<<<(ROWS*Dd)/4096, 256>>>(x, pxh);
    cudaStreamWaitEvent(0, e1a, 0);  // join packed weights
    gemmh<false,__half><<<dim3(VPW/128, ROWS/128), 256, 98304>>>(pxh, pwcat, pbcat, pvph, ROWS, VPW, Dd, VPW);

    cudaStreamWaitEvent(0, e2, 0);   // join gating path
    attn_k<<<dim3(Ss/128, Hh, Bb), 256>>>(pvph, pck, pctxh);

    cudaStreamWaitEvent(0, e1, 0);   // join weight conversions
    gemmh<false,float><<<dim3(Dd/128, ROWS/128), 256, 98304>>>(pctxh, powh, out_b, pao, ROWS, Dd, Dd, Dd);

    ln_k<<<ROWS, 256>>>(x, pao, ln1_g, ln1_b, ph, phch);
    gemmh<true,__half><<<dim3(FFD/128, ROWS/128), 256, 98304>>>(phch,  pw1h, ffn_b1, pffnh, ROWS, FFD, Dd, FFD);
    gemmh<false,float><<<dim3(Dd/128, ROWS/128), 256, 98304>>>(pffnh, pw2h, ffn_b2, pf2,  ROWS, Dd, FFD, Dd);
    ln_k<<<ROWS, 256>>>(ph, pf2, ln2_g, ln2_b, out, nullptr);

    // side streams are joined (events waited on) — safe to release handles
    cudaEventDestroy(e0);
    cudaEventDestroy(e1a);
    cudaEventDestroy(e1);
    cudaEventDestroy(e2);
    cudaStreamDestroy(s1);
    cudaStreamDestroy(s2);
}

// round 14
// speedup vs baseline: 1.1508x; 1.0018x over previous
#include <cuda_runtime.h>
#include <cuda_fp16.h>
#include <math.h>
#include <stdint.h>

// ---------------- problem constants ----------------
#define Bb   2
#define Ss   1024
#define Dd   1024
#define Hh   16
#define HDd  64
#define MMm  16
#define WWw  8
#define RMm  8
#define CRc  8
#define FFD  4096
#define ROWS (Bb*Ss)          // 2048
#define VPW  1408             // v(1024) | qm(16) km(16) qc(128) kc(128) pad

// ---------------- scratch ----------------
__device__ __half g_xh   [ROWS*Dd];
__device__ __half g_wcat [Dd*VPW];
__device__ float  g_bcat [VPW];
__device__ __half g_vph  [ROWS*VPW];
__device__ __half g_owh  [Dd*Dd];
__device__ __half g_w1h  [Dd*FFD];
__device__ __half g_w2h  [FFD*Dd];
__device__ __half g_ctxh [ROWS*Dd];
__device__ __half g_hch  [ROWS*Dd];
__device__ __half g_ffnh [ROWS*FFD];
__device__ float  g_pp   [64*2048];
__device__ float  g_pool [Bb*Dd];
__device__ float  g_wts  [Bb*Hh*MMm];
__device__ float  g_ckr  [Bb*Hh*Ss];
__device__ float  g_ao   [ROWS*Dd];
__device__ float  g_h    [ROWS*Dd];
__device__ float  g_f2   [ROWS*Dd];

// ---------------- helpers ----------------
__device__ __forceinline__ uint32_t smem_u32(const void* p) {
    uint32_t a;
    asm("{ .reg .u64 t; cvta.to.shared.u64 t, %1; cvt.u32.u64 %0, t; }" : "=r"(a) : "l"(p));
    return a;
}
__device__ __forceinline__ void mma_f16(float* c, const uint32_t* a, const uint32_t* b) {
    asm volatile(
        "mma.sync.aligned.m16n8k16.row.col.f32.f16.f16.f32 "
        "{%0,%1,%2,%3}, {%4,%5,%6,%7}, {%8,%9}, {%0,%1,%2,%3};"
        : "+f"(c[0]), "+f"(c[1]), "+f"(c[2]), "+f"(c[3])
        : "r"(a[0]), "r"(a[1]), "r"(a[2]), "r"(a[3]), "r"(b[0]), "r"(b[1]));
}
__device__ __forceinline__ void cpa16(uint32_t dst, const void* src) {
    asm volatile("cp.async.cg.shared.global [%0], [%1], 16;" :: "r"(dst), "l"(src));
}
#define CPA_COMMIT() asm volatile("cp.async.commit_group;" ::: "memory")
__device__ __forceinline__ uint32_t h2u(float a, float b) {
    __half2 h = __floats2half2_rn(a, b);
    return *(uint32_t*)&h;
}
__device__ __forceinline__ void st2(float* p, float a, float b) { *(float2*)p = make_float2(a, b); }
__device__ __forceinline__ void st2(__half* p, float a, float b) { *(__half2*)p = __floats2half2_rn(a, b); }

// ---------------- fp16 GEMM: C[M,0..N) = A[M,K] @ B[K,N] + bias ----------------
// A half K-major; B half row-major [K][N] (stride N). C row stride ldc.
// CTA tile 128 x (NT*128). NT=1: warp tile 64x32 (8 warps 2x4).
// NT=2: warp tile 64x64 (8 warps 2x4 over 256 cols) — 25% less L2 traffic per output.
// K-tile 64, 3-stage cp.async pipeline.
template<int NT, bool GELU, typename OT>
__global__ void __launch_bounds__(256, 2/NT)
gemmh(const __half* __restrict__ A, const __half* __restrict__ B,
      const float* __restrict__ bias, OT* __restrict__ C,
      int M, int N, int K, int ldc)
{
    extern __shared__ __align__(16) unsigned char smem[];
    const int tid = threadIdx.x, lane = tid & 31, warp = tid >> 5;
    const int wm = warp & 1, wn = warp >> 1;
    const int rr = lane >> 2, cl = lane & 3;
    const int m0 = blockIdx.y * 128, n0 = blockIdx.x * (NT * 128);
    const __half* Arow = A + (size_t)m0 * K;
    const __half* Bcol = B + n0;
    const uint32_t sbase = smem_u32(smem);
    const int T = K >> 6;
    const int BROW   = NT * 256;            // B row bytes
    const int BUNITS = NT * 16;             // 16B units per B row
    const int STAGE  = 16384 + 64 * BROW;   // A (16KB) + B

    float acc[4][4*NT][4];
    #pragma unroll
    for (int mt = 0; mt < 4; mt++)
        #pragma unroll
        for (int nt = 0; nt < 4*NT; nt++)
            #pragma unroll
            for (int q = 0; q < 4; q++) acc[mt][nt][q] = 0.f;

    auto stage = [&](int t) {
        if (t < T) {
            const uint32_t sb = sbase + (t % 3) * STAGE;
            const int k0 = t << 6;
            #pragma unroll
            for (int q = 0; q < 4; q++) {
                int ch = q * 256 + tid;
                int row = ch >> 3, u = ch & 7;
                uint32_t off = row * 128 + ((u ^ (row & 7)) << 4);
                cpa16(sb + off, Arow + (size_t)row * K + k0 + u * 8);
            }
            #pragma unroll
            for (int q = 0; q < 4*NT; q++) {
                int ch = q * 256 + tid;
                int k = ch / BUNITS, u = ch % BUNITS;
                uint32_t off = k * BROW + (((u & ~7) | ((u & 7) ^ (k & 7))) << 4);
                cpa16(sb + 16384 + off, Bcol + (size_t)(k0 + k) * N + u * 8);
            }
        }
        CPA_COMMIT();
    };

    stage(0); stage(1);
    for (int t = 0; t < T; t++) {
        asm volatile("cp.async.wait_group 1;" ::: "memory");
        __syncthreads();
        stage(t + 2);
        const uint32_t sA = sbase + (t % 3) * STAGE;
        const uint32_t sB = sA + 16384;

        #pragma unroll
        for (int kk = 0; kk < 4; kk++) {
            uint32_t af[4][4], bf[4*NT][2];
            #pragma unroll
            for (int mt = 0; mt < 4; mt++) {
                int row = wm * 64 + mt * 16 + ((lane >> 3) & 1) * 8 + (lane & 7);
                int unit = kk * 2 + (lane >> 4);
                uint32_t addr = sA + row * 128 + ((unit ^ (row & 7)) << 4);
                asm volatile("ldmatrix.sync.aligned.m8n8.x4.shared.b16 {%0,%1,%2,%3}, [%4];"
                             : "=r"(af[mt][0]), "=r"(af[mt][1]), "=r"(af[mt][2]), "=r"(af[mt][3])
                             : "r"(addr));
            }
            #pragma unroll
            for (int nt = 0; nt < 4*NT; nt += 2) {
                int rowk = kk * 16 + (lane & 15);
                int un = wn * (4*NT) + nt + (lane >> 4);
                uint32_t addr = sB + rowk * BROW + (((un & ~7) | ((un & 7) ^ (rowk & 7))) << 4);
                asm volatile("ldmatrix.sync.aligned.m8n8.x4.trans.shared.b16 {%0,%1,%2,%3}, [%4];"
                             : "=r"(bf[nt][0]), "=r"(bf[nt][1]), "=r"(bf[nt+1][0]), "=r"(bf[nt+1][1])
                             : "r"(addr));
            }
            #pragma unroll
            for (int mt = 0; mt < 4; mt++)
                #pragma unroll
                for (int nt = 0; nt < 4*NT; nt++)
                    mma_f16(acc[mt][nt], af[mt], bf[nt]);
        }
    }

    #pragma unroll
    for (int mt = 0; mt < 4; mt++) {
        #pragma unroll
        for (int nt = 0; nt < 4*NT; nt++) {
            int r  = m0 + wm * 64 + mt * 16 + rr;
            int cc = n0 + wn * (32*NT) + nt * 8 + 2 * cl;
            float b0 = bias ? bias[cc]     : 0.f;
            float b1 = bias ? bias[cc + 1] : 0.f;
            float v0 = acc[mt][nt][0] + b0;
            float v1 = acc[mt][nt][1] + b1;
            float v2 = acc[mt][nt][2] + b0;
            float v3 = acc[mt][nt][3] + b1;
            if (GELU) {
                v0 = 0.5f * v0 * (1.f + erff(v0 * 0.70710678118654752f));
                v1 = 0.5f * v1 * (1.f + erff(v1 * 0.70710678118654752f));
                v2 = 0.5f * v2 * (1.f + erff(v2 * 0.70710678118654752f));
                v3 = 0.5f * v3 * (1.f + erff(v3 * 0.70710678118654752f));
            }
            st2(C + (size_t)r * ldc + cc,       v0, v1);
            st2(C + (size_t)(r + 8) * ldc + cc, v2, v3);
        }
    }
}

// ---------------- prep kernels ----------------
__device__ __forceinline__ void cvt16(const float* __restrict__ src, __half* __restrict__ dst, int i)
{
    float4 v0 = *(const float4*)(src + i);
    float4 v1 = *(const float4*)(src + i + 4);
    float4 v2 = *(const float4*)(src + i + 8);
    float4 v3 = *(const float4*)(src + i + 12);
    uint4 o0, o1;
    o0.x = h2u(v0.x, v0.y); o0.y = h2u(v0.z, v0.w);
    o0.z = h2u(v1.x, v1.y); o0.w = h2u(v1.z, v1.w);
    o1.x = h2u(v2.x, v2.y); o1.y = h2u(v2.z, v2.w);
    o1.z = h2u(v3.x, v3.y); o1.w = h2u(v3.z, v3.w);
    *(uint4*)(dst + i)     = o0;
    *(uint4*)(dst + i + 8) = o1;
}

__global__ void cvth_k(const float* __restrict__ src, __half* __restrict__ dst)
{
    cvt16(src, dst, (blockIdx.x * 256 + threadIdx.x) * 16);
}

__global__ void cvt3_k(const float* __restrict__ a, __half* __restrict__ da,
                       const float* __restrict__ b, __half* __restrict__ db,
                       const float* __restrict__ c, __half* __restrict__ dc)
{
    int blk = blockIdx.x;
    const float* src; __half* dst; int base;
    if      (blk < 256)  { src = a; dst = da; base = blk; }
    else if (blk < 1280) { src = b; dst = db; base = blk - 256; }
    else                 { src = c; dst = dc; base = blk - 1280; }
    cvt16(src, dst, (base * 256 + threadIdx.x) * 16);
}

__global__ void wcat_k(const float* __restrict__ v_w, const float* __restrict__ v_b,
                       const float* __restrict__ qmod_w, const float* __restrict__ qmod_b,
                       const float* __restrict__ kmod_w, const float* __restrict__ kmod_b,
                       const float* __restrict__ cq_w,   const float* __restrict__ ck_w,
                       __half* __restrict__ wcat, float* __restrict__ bcat)
{
    int idx = blockIdx.x * 256 + threadIdx.x;          // over 1024*1408
    int k = idx / VPW, n = idx - k * VPW;
    float v = 0.f;
    if      (n < 1024) v = v_w[k*1024 + n];
    else {
        int c = n - 1024;
        if      (c < 16)  v = qmod_w[k*Hh + c];
        else if (c < 32)  v = kmod_w[k*Hh + (c - 16)];
        else if (c < 160) v = cq_w[k*(Hh*CRc) + (c - 32)];
        else if (c < 288) v = ck_w[k*(Hh*CRc) + (c - 160)];
    }
    wcat[idx] = __float2half_rn(v);
    if (idx < VPW) {
        float bv = 0.f;
        if (idx < 1024) bv = v_b[idx];
        else { int p = idx - 1024; if (p < 16) bv = qmod_b[p]; else if (p < 32) bv = kmod_b[p - 16]; }
        bcat[idx] = bv;
    }
}

// ---------------- pooled mean over S ----------------
__global__ void pool1_k(const float* __restrict__ x, float* __restrict__ pp)
{
    int idx = blockIdx.x * 256 + threadIdx.x;
    int sl  = blockIdx.y;                           // 0..63
    int b = idx >> 10, d = idx & 1023;
    const float* xp = x + (size_t)(b*Ss + sl*16)*Dd + d;
    float s0=0,s1=0;
    #pragma unroll
    for (int q = 0; q < 16; q += 2) {
        s0 += xp[(size_t)(q+0)*Dd];
        s1 += xp[(size_t)(q+1)*Dd];
    }
    pp[sl*2048 + idx] = s0+s1;
}

__global__ void pool2_k(const float* __restrict__ pp, float* __restrict__ pooled)
{
    int idx = blockIdx.x * 256 + threadIdx.x;
    float s = 0.f;
    #pragma unroll
    for (int q = 0; q < 64; q++) s += pp[q*2048 + idx];
    pooled[idx] = s * (1.f/Ss);
}

// ---------------- gating ----------------
__global__ void __launch_bounds__(256) gating_k(const float* __restrict__ pooled,
    const float* __restrict__ gate_w, const float* __restrict__ gate_b,
    const float* __restrict__ mod_w,  const float* __restrict__ mod_b,
    const float* __restrict__ mod_basis, float* __restrict__ wts)
{
    int blk = blockIdx.x;
    int b = blk / Hh, h = blk % Hh;
    int tid = threadIdx.x, warp = tid >> 5, lane = tid & 31;
    __shared__ float ps[Dd];
    __shared__ float outs[24];
    __shared__ float gls[MMm];
    for (int q = tid; q < Dd; q += 256) ps[q] = pooled[b*Dd + q];
    __syncthreads();
    for (int o = warp; o < 24; o += 8) {
        const float* wcol; int stride; float bias;
        if (o < 16) { wcol = gate_w + h*MMm + o;      stride = Hh*MMm; bias = gate_b[h*MMm + o]; }
        else        { int r = o-16; wcol = mod_w + h*RMm + r; stride = Hh*RMm; bias = mod_b[h*RMm + r]; }
        float s = 0.f;
        for (int dI = lane; dI < Dd; dI += 32) s += ps[dI] * wcol[(size_t)dI * stride];
        #pragma unroll
        for (int off = 16; off; off >>= 1) s += __shfl_xor_sync(0xffffffffu, s, off);
        if (lane == 0) outs[o] = s + bias;
    }
    __syncthreads();
    if (tid < MMm) {
        float gl = outs[tid];
        #pragma unroll
        for (int r = 0; r < RMm; r++) gl += outs[16 + r] * mod_basis[(r*Hh + h)*MMm + tid];
        gls[tid] = gl;
    }
    __syncthreads();
    if (tid == 0) {
        float mx = -1e30f;
        for (int m = 0; m < MMm; m++) mx = fmaxf(mx, gls[m]);
        float e[MMm], sm = 0.f;
        for (int m = 0; m < MMm; m++) { e[m] = expf(gls[m] - mx); sm += e[m]; }
        float inv = 1.f / sm;
        for (int m = 0; m < MMm; m++) wts[(b*Hh + h)*MMm + m] = e[m] * inv;
    }
}

// ---------------- wave mask -> causal Toeplitz row ----------------
__global__ void __launch_bounds__(256) wave_k(const float* __restrict__ wts,
    const float* __restrict__ freqs, const float* __restrict__ amps,
    const float* __restrict__ phases, float* __restrict__ ckr)
{
    int b = blockIdx.z, h = blockIdx.y;
    int d = blockIdx.x * 256 + threadIdx.x;
    __shared__ float fs[MMm*WWw*2], as_[MMm*WWw], ph_[MMm*WWw], ws[MMm];
    int t = threadIdx.x;
    fs[t] = freqs[h*MMm*WWw*2 + t];
    if (t < MMm*WWw) { as_[t] = amps[h*MMm*WWw + t]; ph_[t] = phases[h*MMm*WWw + t]; }
    if (t < MMm) ws[t] = wts[(b*Hh + h)*MMm + t];
    __syncthreads();
    float p1 = d * (1.f/Ss);
    float p2 = (d == 0) ? 0.f : sqrtf((float)d + 1e-6f) * 0.03125f;
    float kern = 0.f;
    #pragma unroll
    for (int m = 0; m < MMm; m++) {
        float acc = 0.f;
        #pragma unroll
        for (int w = 0; w < WWw; w++) {
            int iw = m*WWw + w;
            acc += as_[iw] * sinf(fs[iw*2+0]*p1 + fs[iw*2+1]*p2 + ph_[iw]);
        }
        kern += ws[m] * acc;
    }
    float dens = 1.f / (1.f + expf(-6.f * kern));
    float win  = expf(-(float)d * (float)d * (1.f/131072.f));
    ckr[(b*Hh + h)*Ss + d] = 3.f * dens * win;
}

// ---------------- flash attention, tensor-core PV, 128 queries/CTA ----------------
__global__ void __launch_bounds__(256) attn_k(const __half* __restrict__ vp,
    const float* __restrict__ ckr, __half* __restrict__ ctx)
{
    const int b = blockIdx.z, h = blockIdx.y;
    const int qb = (gridDim.x - 1 - blockIdx.x) * 128;     // big tiles first
    const int tid = threadIdx.x, warp = tid >> 5, lane = tid & 31;
    const int g = lane >> 2, c2 = (lane & 3) * 2;

    __shared__ float  ck_s[Ss];
    __shared__ __half km_s[Ss];
    __shared__ __align__(16) __half vsm[2][64*64];     // [j][d] 128B rows, swizzled
    __shared__ __align__(16) __half kcs[2][64*8];      // [j][8] 16B rows

    const __half* vpB = vp + (size_t)(b*Ss) * VPW;
    for (int o = tid; o < Ss; o += 256) {
        ck_s[o] = ckr[(b*Hh + h)*Ss + o];
        km_s[o] = vpB[(size_t)o*VPW + 1040 + h];
    }

    const float cmix = 0.0530330085889911f;
    const int i_lo = qb + warp*16 + g, i_hi = i_lo + 8;
    uint32_t aq[4];
    {
        float qlo0 = cmix * __half2float(vpB[(size_t)i_lo*VPW + 1056 + h*CRc + c2]);
        float qlo1 = cmix * __half2float(vpB[(size_t)i_lo*VPW + 1056 + h*CRc + c2 + 1]);
        float qhi0 = cmix * __half2float(vpB[(size_t)i_hi*VPW + 1056 + h*CRc + c2]);
        float qhi1 = cmix * __half2float(vpB[(size_t)i_hi*VPW + 1056 + h*CRc + c2 + 1]);
        aq[0] = h2u(qlo0, qlo1);
        aq[1] = h2u(qhi0, qhi1);
        if ((lane & 3) == 0) {
            aq[2] = h2u(1.f, __half2float(vpB[(size_t)i_lo*VPW + 1024 + h]));
            aq[3] = h2u(1.f, __half2float(vpB[(size_t)i_hi*VPW + 1024 + h]));
        } else { aq[2] = 0; aq[3] = 0; }
    }

    float m_lo = -1e30f, m_hi = -1e30f, l_lo = 0.f, l_hi = 0.f;
    float o_[8][4];
    #pragma unroll
    for (int nt = 0; nt < 8; nt++)
        #pragma unroll
        for (int q = 0; q < 4; q++) o_[nt][q] = 0.f;

    const int iwmax = qb + warp*16 + 15;
    const int nblk = qb/64 + 2;
    const uint32_t vbase = smem_u32(vsm);
    const uint32_t kbase = smem_u32(kcs);

    auto stage = [&](int t) {
        if (t < nblk) {
            const int jb = t * 64;
            const uint32_t vb = vbase + (t & 1) * 8192;
            const uint32_t kb = kbase + (t & 1) * 1024;
            #pragma unroll
            for (int q = 0; q < 2; q++) {
                int ch = q * 256 + tid;
                int j = ch >> 3, u = ch & 7;
                cpa16(vb + j*128 + ((u ^ (j & 7)) << 4),
                      vpB + (size_t)(jb + j)*VPW + h*HDd + u*8);
            }
            if (tid < 64)
                cpa16(kb + tid*16, vpB + (size_t)(jb + tid)*VPW + 1184 + h*CRc);
        }
        CPA_COMMIT();
    };

    stage(0);
    const __half one_h = __float2half_rn(1.f);
    for (int t = 0; t < nblk; t++) {
        const int jb = t * 64;
        stage(t + 1);
        asm volatile("cp.async.wait_group 1;" ::: "memory");
        __syncthreads();

        if (jb <= iwmax) {
            const uint32_t vb = vbase + (t & 1) * 8192;
            const __half* kcb = &kcs[t & 1][0];
            float s[8][4];
            #pragma unroll
            for (int nt = 0; nt < 8; nt++) {
                s[nt][0] = s[nt][1] = s[nt][2] = s[nt][3] = 0.f;
                uint32_t kb2[2];
                kb2[0] = *(const uint32_t*)((const char*)(kcb + (nt*8 + g)*8) + (lane & 3)*4);
                if ((lane & 3) == 0) {
                    __half2 hh = __halves2half2(km_s[jb + nt*8 + g], one_h);
                    kb2[1] = *(uint32_t*)&hh;
                } else kb2[1] = 0;
                mma_f16(s[nt], aq, kb2);
            }
            const int irl = i_lo - jb, irh = irl + 8;
            const bool mlo = (irl < 63), mhi = (irh < 63);
            #pragma unroll
            for (int nt = 0; nt < 8; nt++) {
                int j0 = nt*8 + c2;
                if (!mlo) {
                    s[nt][0] += ck_s[irl - j0];
                    s[nt][1] += ck_s[irl - j0 - 1];
                } else {
                    s[nt][0] = (j0     <= irl) ? s[nt][0] + ck_s[irl - j0]     : -1e30f;
                    s[nt][1] = (j0 + 1 <= irl) ? s[nt][1] + ck_s[irl - j0 - 1] : -1e30f;
                }
                if (!mhi) {
                    s[nt][2] += ck_s[irh - j0];
                    s[nt][3] += ck_s[irh - j0 - 1];
                } else {
                    s[nt][2] = (j0     <= irh) ? s[nt][2] + ck_s[irh - j0]     : -1e30f;
                    s[nt][3] = (j0 + 1 <= irh) ? s[nt][3] + ck_s[irh - j0 - 1] : -1e30f;
                }
            }
            float mx_lo = -1e30f, mx_hi = -1e30f;
            #pragma unroll
            for (int nt = 0; nt < 8; nt++) {
                mx_lo = fmaxf(mx_lo, fmaxf(s[nt][0], s[nt][1]));
                mx_hi = fmaxf(mx_hi, fmaxf(s[nt][2], s[nt][3]));
            }
            mx_lo = fmaxf(mx_lo, __shfl_xor_sync(0xffffffffu, mx_lo, 1));
            mx_lo = fmaxf(mx_lo, __shfl_xor_sync(0xffffffffu, mx_lo, 2));
            mx_hi = fmaxf(mx_hi, __shfl_xor_sync(0xffffffffu, mx_hi, 1));
            mx_hi = fmaxf(mx_hi, __shfl_xor_sync(0xffffffffu, mx_hi, 2));
            float mn_lo = fmaxf(m_lo, mx_lo), mn_hi = fmaxf(m_hi, mx_hi);
            float sc_lo = __expf(m_lo - mn_lo), sc_hi = __expf(m_hi - mn_hi);
            float p[8][4], sum_lo = 0.f, sum_hi = 0.f;
            #pragma unroll
            for (int nt = 0; nt < 8; nt++) {
                p[nt][0] = __expf(s[nt][0] - mn_lo);
                p[nt][1] = __expf(s[nt][1] - mn_lo);
                p[nt][2] = __expf(s[nt][2] - mn_hi);
                p[nt][3] = __expf(s[nt][3] - mn_hi);
                sum_lo += p[nt][0] + p[nt][1];
                sum_hi += p[nt][2] + p[nt][3];
            }
            sum_lo += __shfl_xor_sync(0xffffffffu, sum_lo, 1);
            sum_lo += __shfl_xor_sync(0xffffffffu, sum_lo, 2);
            sum_hi += __shfl_xor_sync(0xffffffffu, sum_hi, 1);
            sum_hi += __shfl_xor_sync(0xffffffffu, sum_hi, 2);
            l_lo = l_lo * sc_lo + sum_lo;  m_lo = mn_lo;
            l_hi = l_hi * sc_hi + sum_hi;  m_hi = mn_hi;
            #pragma unroll
            for (int nt = 0; nt < 8; nt++) {
                o_[nt][0] *= sc_lo; o_[nt][1] *= sc_lo;
                o_[nt][2] *= sc_hi; o_[nt][3] *= sc_hi;
            }
            #pragma unroll
            for (int kt = 0; kt < 4; kt++) {
                uint32_t pa[4];
                pa[0] = h2u(p[2*kt][0],   p[2*kt][1]);
                pa[1] = h2u(p[2*kt][2],   p[2*kt][3]);
                pa[2] = h2u(p[2*kt+1][0], p[2*kt+1][1]);
                pa[3] = h2u(p[2*kt+1][2], p[2*kt+1][3]);
                uint32_t bf[8][2];
                #pragma unroll
                for (int nt = 0; nt < 8; nt += 2) {
                    int row = kt*16 + (lane & 15);
                    int unit = nt + (lane >> 4);
                    uint32_t addr = vb + row*128 + ((unit ^ (row & 7)) << 4);
                    asm volatile("ldmatrix.sync.aligned.m8n8.x4.trans.shared.b16 {%0,%1,%2,%3}, [%4];"
                                 : "=r"(bf[nt][0]), "=r"(bf[nt][1]), "=r"(bf[nt+1][0]), "=r"(bf[nt+1][1])
                                 : "r"(addr));
                }
                #pragma unroll
                for (int nt = 0; nt < 8; nt++)
                    mma_f16(o_[nt], pa, bf[nt]);
            }
        }
        __syncthreads();
    }

    float inv_lo = 1.f / l_lo, inv_hi = 1.f / l_hi;
    #pragma unroll
    for (int nt = 0; nt < 8; nt++) {
        __half2* plo = (__half2*)(ctx + (size_t)(b*Ss + i_lo)*Dd + h*HDd + nt*8 + c2);
        __half2* phi = (__half2*)(ctx + (size_t)(b*Ss + i_hi)*Dd + h*HDd + nt*8 + c2);
        *plo = __floats2half2_rn(o_[nt][0]*inv_lo, o_[nt][1]*inv_lo);
        *phi = __floats2half2_rn(o_[nt][2]*inv_hi, o_[nt][3]*inv_hi);
    }
}

// ---------------- fused residual + LayerNorm ----------------
__global__ void __launch_bounds__(256) ln_k(const float* __restrict__ a,
    const float* __restrict__ r, const float* __restrict__ g,
    const float* __restrict__ bta, float* __restrict__ out, __half* __restrict__ out2)
{
    int row = blockIdx.x;
    size_t base = (size_t)row * Dd;
    int tid = threadIdx.x;
    float vals[4], s = 0.f, s2 = 0.f;
    #pragma unroll
    for (int q = 0; q < 4; q++) {
        int idx = tid + q*256;
        float xv = a[base + idx] + r[base + idx];
        vals[q] = xv; s += xv; s2 += xv*xv;
    }
    __shared__ float red[64];
    #pragma unroll
    for (int o = 16; o; o >>= 1) {
        s  += __shfl_xor_sync(0xffffffffu, s,  o);
        s2 += __shfl_xor_sync(0xffffffffu, s2, o);
    }
    int warp = tid >> 5, lane = tid & 31;
    if (lane == 0) { red[warp] = s; red[32 + warp] = s2; }
    __syncthreads();
    if (warp == 0) {
        float a1 = (lane < 8) ? red[lane] : 0.f;
        float a2 = (lane < 8) ? red[32 + lane] : 0.f;
        #pragma unroll
        for (int o = 4; o; o >>= 1) {
            a1 += __shfl_xor_sync(0xffffffffu, a1, o);
            a2 += __shfl_xor_sync(0xffffffffu, a2, o);
        }
        if (lane == 0) { red[0] = a1; red[1] = a2; }
    }
    __syncthreads();
    float mean = red[0] * (1.f/Dd);
    float var  = red[1] * (1.f/Dd) - mean*mean;
    float rstd = rsqrtf(var + 1e-5f);
    #pragma unroll
    for (int q = 0; q < 4; q++) {
        int idx = tid + q*256;
        float o = (vals[q] - mean) * rstd * g[idx] + bta[idx];
        out[base + idx] = o;
        if (out2) out2[base + idx] = __float2half_rn(o);
    }
}

// ---------------- launch ----------------
extern "C" void kernel_launch(void* const* d_in, const int* in_sizes, int n_in,
                              void* d_out, int out_size)
{
    const float* x      = (const float*)d_in[0];
    const float* v_w    = (const float*)d_in[1];
    const float* v_b    = (const float*)d_in[2];
    const float* out_w  = (const float*)d_in[3];
    const float* out_b  = (const float*)d_in[4];
    const float* qmod_w = (const float*)d_in[5];
    const float* qmod_b = (const float*)d_in[6];
    const float* kmod_w = (const float*)d_in[7];
    const float* kmod_b = (const float*)d_in[8];
    const float* gate_w = (const float*)d_in[9];
    const float* gate_b = (const float*)d_in[10];
    const float* mod_w  = (const float*)d_in[11];
    const float* mod_b  = (const float*)d_in[12];
    const float* mod_basis = (const float*)d_in[13];
    const float* freqs  = (const float*)d_in[14];
    const float* amps   = (const float*)d_in[15];
    const float* phases = (const float*)d_in[16];
    const float* cq_w   = (const float*)d_in[17];
    const float* ck_w   = (const float*)d_in[18];
    const float* ffn_w1 = (const float*)d_in[19];
    const float* ffn_b1 = (const float*)d_in[20];
    const float* ffn_w2 = (const float*)d_in[21];
    const float* ffn_b2 = (const float*)d_in[22];
    const float* ln1_g  = (const float*)d_in[23];
    const float* ln1_b  = (const float*)d_in[24];
    const float* ln2_g  = (const float*)d_in[25];
    const float* ln2_b  = (const float*)d_in[26];
    float* out = (float*)d_out;

    __half *pxh, *pwcat, *pvph, *powh, *pw1h, *pw2h, *pctxh, *phch, *pffnh;
    float *pbcat, *ppp, *ppool, *pwts, *pck, *pao, *ph, *pf2;
    cudaGetSymbolAddress((void**)&pxh,  g_xh);
    cudaGetSymbolAddress((void**)&pwcat,g_wcat);
    cudaGetSymbolAddress((void**)&pbcat,g_bcat);
    cudaGetSymbolAddress((void**)&pvph, g_vph);
    cudaGetSymbolAddress((void**)&powh, g_owh);
    cudaGetSymbolAddress((void**)&pw1h, g_w1h);
    cudaGetSymbolAddress((void**)&pw2h, g_w2h);
    cudaGetSymbolAddress((void**)&pctxh,g_ctxh);
    cudaGetSymbolAddress((void**)&phch, g_hch);
    cudaGetSymbolAddress((void**)&pffnh,g_ffnh);
    cudaGetSymbolAddress((void**)&ppp,  g_pp);
    cudaGetSymbolAddress((void**)&ppool,g_pool);
    cudaGetSymbolAddress((void**)&pwts, g_wts);
    cudaGetSymbolAddress((void**)&pck,  g_ckr);
    cudaGetSymbolAddress((void**)&pao,  g_ao);
    cudaGetSymbolAddress((void**)&ph,   g_h);
    cudaGetSymbolAddress((void**)&pf2,  g_f2);

    cudaFuncSetAttribute(gemmh<1,false,__half>, cudaFuncAttributeMaxDynamicSharedMemorySize, 98304);
    cudaFuncSetAttribute(gemmh<1,false,float>,  cudaFuncAttributeMaxDynamicSharedMemorySize, 98304);
    cudaFuncSetAttribute(gemmh<2,true,__half>,  cudaFuncAttributeMaxDynamicSharedMemorySize, 147456);

    // fork two side streams inside the capture (kernels + events only)
    cudaStream_t s1, s2;
    cudaStreamCreateWithFlags(&s1, cudaStreamNonBlocking);
    cudaStreamCreateWithFlags(&s2, cudaStreamNonBlocking);
    cudaEvent_t e0, e1a, e1, e2;
    cudaEventCreateWithFlags(&e0,  cudaEventDisableTiming);
    cudaEventCreateWithFlags(&e1a, cudaEventDisableTiming);
    cudaEventCreateWithFlags(&e1,  cudaEventDisableTiming);
    cudaEventCreateWithFlags(&e2,  cudaEventDisableTiming);
    cudaEventRecord(e0, 0);
    cudaStreamWaitEvent(s1, e0, 0);
    cudaStreamWaitEvent(s2, e0, 0);

    // s1: fused-v weight pack (joined before vp GEMM), then FFN/out-proj conversions
    wcat_k<<<(Dd*VPW)/256, 256, 0, s1>>>(v_w, v_b, qmod_w, qmod_b, kmod_w, kmod_b, cq_w, ck_w, pwcat, pbcat);
    cudaEventRecord(e1a, s1);
    cvt3_k<<<2304, 256, 0, s1>>>(out_w, powh, ffn_w1, pw1h, ffn_w2, pw2h);
    cudaEventRecord(e1, s1);

    // s2: gating path (joined before attention)
    pool1_k<<<dim3(8,64), 256, 0, s2>>>(x, ppp);
    pool2_k<<<8, 256, 0, s2>>>(ppp, ppool);
    gating_k<<<Bb*Hh, 256, 0, s2>>>(ppool, gate_w, gate_b, mod_w, mod_b, mod_basis, pwts);
    wave_k<<<dim3(Ss/256, Hh, Bb), 256, 0, s2>>>(pwts, freqs, amps, phases, pck);
    cudaEventRecord(e2, s2);

    // s0: main chain
    cvth_k<<<(ROWS*Dd)/4096, 256>>>(x, pxh);
    cudaStreamWaitEvent(0, e1a, 0);  // join packed weights
    gemmh<1,false,__half><<<dim3(VPW/128, ROWS/128), 256, 98304>>>(pxh, pwcat, pbcat, pvph, ROWS, VPW, Dd, VPW);

    cudaStreamWaitEvent(0, e2, 0);   // join gating path
    attn_k<<<dim3(Ss/128, Hh, Bb), 256>>>(pvph, pck, pctxh);

    cudaStreamWaitEvent(0, e1, 0);   // join weight conversions
    gemmh<1,false,float><<<dim3(Dd/128, ROWS/128), 256, 98304>>>(pctxh, powh, out_b, pao, ROWS, Dd, Dd, Dd);

    ln_k<<<ROWS, 256>>>(x, pao, ln1_g, ln1_b, ph, phch);
    gemmh<2,true,__half><<<dim3(FFD/256, ROWS/128), 256, 147456>>>(phch,  pw1h, ffn_b1, pffnh, ROWS, FFD, Dd, FFD);
    gemmh<1,false,float><<<dim3(Dd/128, ROWS/128), 256, 98304>>>(pffnh, pw2h, ffn_b2, pf2,  ROWS, Dd, FFD, Dd);
    ln_k<<<ROWS, 256>>>(ph, pf2, ln2_g, ln2_b, out, nullptr);

    // side streams are joined (events waited on) — safe to release handles
    cudaEventDestroy(e0);
    cudaEventDestroy(e1a);
    cudaEventDestroy(e1);
    cudaEventDestroy(e2);
    cudaStreamDestroy(s1);
    cudaStreamDestroy(s2);
}